// round 7
// baseline (speedup 1.0000x reference)
#include <cuda_runtime.h>
#include <math.h>
#include <stdint.h>

#define B_   1024
#define S_   1024
#define D_   2048
#define OUTW 8192

#define TM 128
#define TN 64
#define NSTAGE 3
// smem per stage: Aa 8KB + Ab 8KB + Ba 4KB + Bb 4KB = 24KB
#define ATILE 8192
#define BTILE 4096
#define STG   24576
#define SMEMB (NSTAGE * STG)

// ---------------- device scratch ----------------
// quantized weights (a=hi digit, b=lo digit), row-major [N][K]
__device__ __align__(128) signed char g_Wp1a[2048u*2048u], g_Wp1b[2048u*2048u];
__device__ __align__(128) signed char g_Wia [6144u*2048u], g_Wib [6144u*2048u];
__device__ __align__(128) signed char g_Wha [6144u*2048u], g_Whb [6144u*2048u];
__device__ __align__(128) signed char g_Wp2a[2048u*2048u], g_Wp2b[2048u*2048u];
__device__ __align__(128) signed char g_Wcpa[2048u*2048u], g_Wcpb[2048u*2048u];
__device__ __align__(128) signed char g_Wq1a[2048u*4096u], g_Wq1b[2048u*4096u];
__device__ __align__(128) signed char g_Wq2a[2048u*2048u], g_Wq2b[2048u*2048u];
__device__ __align__(128) signed char g_Wcqa[2048u*2048u], g_Wcqb[2048u*2048u];
__device__ float g_sWp1[2048], g_sWi[6144], g_sWh[6144], g_sWp2[2048];
__device__ float g_sWcp[2048], g_sWq1[2048], g_sWq2[2048], g_sWcq[2048];
// quantized activations
__device__ __align__(128) signed char g_Xa [B_*2048u], g_Xb [B_*2048u];
__device__ __align__(128) signed char g_Pa [B_*2048u], g_Pb [B_*2048u];
__device__ __align__(128) signed char g_h1a[B_*2048u], g_h1b[B_*2048u];
__device__ __align__(128) signed char g_dta[B_*2048u], g_dtb[B_*2048u];
__device__ __align__(128) signed char g_h2a[B_*2048u], g_h2b[B_*2048u];
__device__ __align__(128) signed char g_h2qa[B_*2048u], g_h2qb[B_*2048u];
__device__ __align__(128) signed char g_Xqa[B_*4096u], g_Xqb[B_*4096u];
__device__ __align__(128) signed char g_dqa[B_*2048u], g_dqb[B_*2048u];
__device__ float g_sX[B_], g_sP[B_], g_sh1[B_], g_sdt[B_], g_sh2[B_], g_sh2q[B_], g_sXq[B_], g_sdq[B_];
// fp32 scratch
__device__ __align__(128) float g_gi[B_*6144u];
__device__ __align__(128) float g_gh[B_*6144u];
__device__ __align__(128) float g_Xf [B_*2048u];
__device__ __align__(128) float g_Xqf[B_*4096u];
__device__ __align__(128) float g_h1f[B_*2048u];
__device__ __align__(128) float g_h2f[B_*2048u];
__device__ __align__(128) float g_h2qf[B_*2048u];
__device__ __align__(128) float g_detf[B_*2048u];
__device__ __align__(128) float g_dqf[B_*2048u];
__device__ float g_bcp[2048], g_ccp[2048], g_bcq[2048], g_ccq[2048];

// ---------------- helpers ----------------
__device__ __forceinline__ float sigmoidf_(float x) { return 1.0f / (1.0f + expf(-x)); }
__device__ __forceinline__ float softplusf_(float x) {
    return fmaxf(x, 0.0f) + log1pf(expf(-fabsf(x)));
}
__device__ __forceinline__ uint32_t smem_u32(const void* p) {
    uint32_t a;
    asm("{ .reg .u64 t; cvta.to.shared.u64 t, %1; cvt.u32.u64 %0, t; }" : "=r"(a) : "l"(p));
    return a;
}
__device__ __forceinline__ void cp16(uint32_t s, const void* g) {
    asm volatile("cp.async.cg.shared.global [%0], [%1], 16;" :: "r"(s), "l"(g));
}
__device__ __forceinline__ void cpcommit() { asm volatile("cp.async.commit_group;" ::: "memory"); }
__device__ __forceinline__ void cpwait1() { asm volatile("cp.async.wait_group 1;" ::: "memory"); }
__device__ __forceinline__ void cpwait0() { asm volatile("cp.async.wait_group 0;" ::: "memory"); }
__device__ __forceinline__ void ldm_x4(uint32_t* r, uint32_t addr) {
    asm volatile("ldmatrix.sync.aligned.m8n8.x4.shared.b16 {%0,%1,%2,%3}, [%4];"
                 : "=r"(r[0]), "=r"(r[1]), "=r"(r[2]), "=r"(r[3]) : "r"(addr));
}
__device__ __forceinline__ void imma_s8(int* c, const uint32_t* a, const uint32_t* b) {
    asm volatile(
        "mma.sync.aligned.m16n8k32.row.col.s32.s8.s8.s32 "
        "{%0,%1,%2,%3}, {%4,%5,%6,%7}, {%8,%9}, {%0,%1,%2,%3};"
        : "+r"(c[0]), "+r"(c[1]), "+r"(c[2]), "+r"(c[3])
        : "r"(a[0]), "r"(a[1]), "r"(a[2]), "r"(a[3]), "r"(b[0]), "r"(b[1]));
}
// smem tile addressing: rows of 64 bytes, swizzled 16B chunks (kc 0..3)
__device__ __forceinline__ uint32_t tadr(uint32_t base, int row, int kc) {
    return base + (uint32_t)(row * 64) + (uint32_t)((kc ^ ((row >> 1) & 3)) << 4);
}
__device__ __forceinline__ void quant1(float v, float rs, signed char& a, signed char& b) {
    float qf = fminf(fmaxf(v * rs, -16256.0f), 16256.0f);
    int q = __float2int_rn(qf);
    int ai = (q + 64) >> 7;
    int bi = q - (ai << 7);
    a = (signed char)ai; b = (signed char)bi;
}

// ---------------- int8 split IMMA GEMM ----------------
// C[M=1024,N] = epi( sA[m]*sB[n]*(16384*aa + 128*(ab+ba)) + bias (+csum) )
// A planes [M][K] int8, B planes [N][K] int8 (weights transposed).
// epi: 0 linear, 1 relu, 2 fused mu/std (col<S_ linear, else softplus(+csum)+1e-4)
__global__ void __launch_bounds__(256) gemm_imma(
    const signed char* __restrict__ Aa, const signed char* __restrict__ Ab,
    const signed char* __restrict__ Ba, const signed char* __restrict__ Bb,
    const float* __restrict__ sA, const float* __restrict__ sB,
    const float* __restrict__ bias, const float* __restrict__ csum,
    float* __restrict__ Cf, int K, int ldc, int epi)
{
    extern __shared__ __align__(1024) char smem[];
    const uint32_t sb = smem_u32(smem);
    const int tid = threadIdx.x;
    const int lane = tid & 31, wid = tid >> 5;
    const int wr = wid >> 2, wc = wid & 3;    // warp tile: 64(M) x 16(N)
    const int bm = blockIdx.y * TM;
    const int bn = blockIdx.x * TN;
    const int g = lane >> 3, i8 = lane & 7;

    int acc1[4][2][4], acc2[4][2][4];
#pragma unroll
    for (int a = 0; a < 4; a++)
#pragma unroll
        for (int b = 0; b < 2; b++)
#pragma unroll
            for (int k = 0; k < 4; k++) { acc1[a][b][k] = 0; acc2[a][b][k] = 0; }

    auto load_stage = [&](uint32_t sbase, int kpos) {
#pragma unroll
        for (int q = tid; q < 512; q += 256) {
            int row = q >> 2, kc = q & 3;
            uint32_t so = tadr(0, row, kc);
            size_t go = (size_t)(bm + row) * K + kpos + kc * 16;
            cp16(sbase + so, Aa + go);
            cp16(sbase + ATILE + so, Ab + go);
        }
        {
            int row = tid >> 2, kc = tid & 3;   // 256 threads cover 64 rows x 4 kc
            uint32_t so = tadr(0, row, kc);
            size_t go = (size_t)(bn + row) * K + kpos + kc * 16;
            cp16(sbase + 2 * ATILE + so, Ba + go);
            cp16(sbase + 2 * ATILE + BTILE + so, Bb + go);
        }
        cpcommit();
    };

    load_stage(sb, 0);
    load_stage(sb + STG, 64);

    const int nk = K / 64;                    // 64 int8 per chunk (2 k32 steps)
    const int aRowBase = wr * 64 + (g & 1) * 8 + i8;
    const int aKsel = g >> 1;
    const int bRowBase = wc * 16 + (g >> 1) * 8 + i8;
    const int bKsel = g & 1;

    int bufc = 0, bufl = 2;
    for (int s = 0; s < nk; s++) {
        if (s < nk - 1) cpwait1(); else cpwait0();
        __syncthreads();
        if (s + 2 < nk) load_stage(sb + (uint32_t)bufl * STG, (s + 2) * 64);

        const uint32_t base = sb + (uint32_t)bufc * STG;
        const uint32_t bAa = base, bAb = base + ATILE;
        const uint32_t bBa = base + 2 * ATILE, bBb = base + 2 * ATILE + BTILE;

#pragma unroll
        for (int step = 0; step < 2; step++) {
            const int c0 = step * 2;
            uint32_t Bfa[2][2], Bfb[2][2];
            {
                uint32_t r[4];
                int kc = c0 + bKsel;
                ldm_x4(r, tadr(bBa, bRowBase, kc));
                Bfa[0][0] = r[0]; Bfa[0][1] = r[1];
                Bfa[1][0] = r[2]; Bfa[1][1] = r[3];
                ldm_x4(r, tadr(bBb, bRowBase, kc));
                Bfb[0][0] = r[0]; Bfb[0][1] = r[1];
                Bfb[1][0] = r[2]; Bfb[1][1] = r[3];
            }
#pragma unroll
            for (int am = 0; am < 4; am++) {
                uint32_t Afa[4], Afb[4];
                int arow = aRowBase + am * 16;
                int kc = c0 + aKsel;
                ldm_x4(Afa, tadr(bAa, arow, kc));
                ldm_x4(Afb, tadr(bAb, arow, kc));
#pragma unroll
                for (int bnf = 0; bnf < 2; bnf++) imma_s8(acc1[am][bnf], Afa, Bfa[bnf]);
#pragma unroll
                for (int bnf = 0; bnf < 2; bnf++) imma_s8(acc2[am][bnf], Afa, Bfb[bnf]);
#pragma unroll
                for (int bnf = 0; bnf < 2; bnf++) imma_s8(acc2[am][bnf], Afb, Bfa[bnf]);
            }
        }
        bufc = (bufc == 2) ? 0 : bufc + 1;
        bufl = (bufl == 2) ? 0 : bufl + 1;
    }

    // ---------------- epilogue ----------------
    const int rQ = lane >> 2;
    const int cP = (lane & 3) * 2;
#pragma unroll
    for (int am = 0; am < 4; am++) {
        const int r0 = bm + wr * 64 + am * 16 + rQ;
        const float sa0 = sA[r0], sa8 = sA[r0 + 8];
#pragma unroll
        for (int bnf = 0; bnf < 2; bnf++) {
            const int c = bn + wc * 16 + bnf * 8 + cP;
            const float sb0 = sB[c], sb1 = sB[c + 1];
            float f0 = 16384.0f * __int2float_rn(acc1[am][bnf][0]) + 128.0f * __int2float_rn(acc2[am][bnf][0]);
            float f1 = 16384.0f * __int2float_rn(acc1[am][bnf][1]) + 128.0f * __int2float_rn(acc2[am][bnf][1]);
            float f2 = 16384.0f * __int2float_rn(acc1[am][bnf][2]) + 128.0f * __int2float_rn(acc2[am][bnf][2]);
            float f3 = 16384.0f * __int2float_rn(acc1[am][bnf][3]) + 128.0f * __int2float_rn(acc2[am][bnf][3]);
            float v0 = sa0 * sb0 * f0 + bias[c];
            float v1 = sa0 * sb1 * f1 + bias[c + 1];
            float v2 = sa8 * sb0 * f2 + bias[c];
            float v3 = sa8 * sb1 * f3 + bias[c + 1];
            if (epi == 1) {
                v0 = fmaxf(v0, 0.0f); v1 = fmaxf(v1, 0.0f);
                v2 = fmaxf(v2, 0.0f); v3 = fmaxf(v3, 0.0f);
            } else if (epi == 2 && c >= S_) {
                const float cs0 = csum[c], cs1 = csum[c + 1];
                v0 = softplusf_(v0 + cs0) + 1e-4f;
                v1 = softplusf_(v1 + cs1) + 1e-4f;
                v2 = softplusf_(v2 + cs0) + 1e-4f;
                v3 = softplusf_(v3 + cs1) + 1e-4f;
            }
            float2 w01; w01.x = v0; w01.y = v1;
            float2 w23; w23.x = v2; w23.y = v3;
            *reinterpret_cast<float2*>(Cf + (size_t)r0 * ldc + c) = w01;
            *reinterpret_cast<float2*>(Cf + (size_t)(r0 + 8) * ldc + c) = w23;
        }
    }
}

// ---------------- per-column |max| of W (scale per output row of W^T) ----------------
__global__ void colmax_k(const float* __restrict__ W, int K, int N,
                         float* __restrict__ sW, int roff)
{
    int n = blockIdx.x * 256 + threadIdx.x;
    float m = 0.0f;
    for (int k = 0; k < K; k += 8) {
#pragma unroll
        for (int u = 0; u < 8; u++)
            m = fmaxf(m, fabsf(W[(size_t)(k + u) * N + n]));
    }
    sW[roff + n] = fmaxf(m, 1e-30f) / 16256.0f;
}

// ---------------- transpose + quantize: T[n][k] = quant(W[k][n]) ----------------
// grid (N/32, K/64), block (32,8)
__global__ void transpose_quant(const float* __restrict__ W, int K, int N,
                                signed char* __restrict__ Ta, signed char* __restrict__ Tb,
                                const float* __restrict__ sW, int ldT, int roff)
{
    __shared__ float t[64][33];
    const int n0 = blockIdx.x * 32, k0 = blockIdx.y * 64;
    const int tx = threadIdx.x, ty = threadIdx.y;
#pragma unroll
    for (int r = 0; r < 64; r += 8)
        t[ty + r][tx] = W[(size_t)(k0 + ty + r) * N + n0 + tx];
    __syncthreads();
#pragma unroll
    for (int r = 0; r < 32; r += 8) {
        const int n = r + ty;
        const float rs = 1.0f / sW[roff + n0 + n];
        float v0 = t[2 * tx][n], v1 = t[2 * tx + 1][n];
        signed char a0, b0, a1, b1;
        quant1(v0, rs, a0, b0);
        quant1(v1, rs, a1, b1);
        size_t o = (size_t)(roff + n0 + n) * ldT + k0 + 2 * tx;
        Ta[o] = a0; Ta[o + 1] = a1;
        Tb[o] = b0; Tb[o + 1] = b1;
    }
}

// ---------------- bias concat + 0.54*colsum of reconstructed W ----------------
__global__ void colprep_q(const float* __restrict__ bmu, const float* __restrict__ bstd,
                          const signed char* __restrict__ Ta, const signed char* __restrict__ Tb,
                          const float* __restrict__ sW, int K,
                          float* __restrict__ bcat, float* __restrict__ ccat)
{
    const int n = blockIdx.x;
    if (n < S_) {
        if (threadIdx.x == 0) { bcat[n] = bmu[n]; ccat[n] = 0.0f; }
        return;
    }
    __shared__ int red[256];
    const signed char* ra = Ta + (size_t)n * K;
    const signed char* rb = Tb + (size_t)n * K;
    int s = 0;
    for (int k = threadIdx.x * 4; k < K; k += 1024) {
        char4 a = *reinterpret_cast<const char4*>(ra + k);
        char4 b = *reinterpret_cast<const char4*>(rb + k);
        s += 128 * ((int)a.x + a.y + a.z + a.w) + ((int)b.x + b.y + b.z + b.w);
    }
    red[threadIdx.x] = s;
    __syncthreads();
    for (int st = 128; st; st >>= 1) {
        if (threadIdx.x < st) red[threadIdx.x] += red[threadIdx.x + st];
        __syncthreads();
    }
    if (threadIdx.x == 0) {
        bcat[n] = bstd[n - S_];
        ccat[n] = 0.54f * sW[n] * (float)red[0];
    }
}

// ---------------- per-row quantize of an fp32 activation tensor ----------------
__global__ void quant_rows(const float* __restrict__ src, int W,
                           signed char* __restrict__ Qa, signed char* __restrict__ Qb,
                           float* __restrict__ sA)
{
    const int row = blockIdx.x;
    const float* r = src + (size_t)row * W;
    __shared__ float red[256];
    float m = 0.0f;
    for (int j = threadIdx.x * 4; j < W; j += 1024) {
        float4 v = *reinterpret_cast<const float4*>(r + j);
        m = fmaxf(m, fmaxf(fmaxf(fabsf(v.x), fabsf(v.y)), fmaxf(fabsf(v.z), fabsf(v.w))));
    }
    red[threadIdx.x] = m;
    __syncthreads();
    for (int st = 128; st; st >>= 1) {
        if (threadIdx.x < st) red[threadIdx.x] = fmaxf(red[threadIdx.x], red[threadIdx.x + st]);
        __syncthreads();
    }
    const float mx = fmaxf(red[0], 1e-30f);
    const float s = mx / 16256.0f, rs = 16256.0f / mx;
    if (threadIdx.x == 0) sA[row] = s;
    for (int j = threadIdx.x * 4; j < W; j += 1024) {
        float4 v = *reinterpret_cast<const float4*>(r + j);
        signed char a0,b0,a1,b1,a2,b2,a3,b3;
        quant1(v.x, rs, a0, b0); quant1(v.y, rs, a1, b1);
        quant1(v.z, rs, a2, b2); quant1(v.w, rs, a3, b3);
        char4 ca; ca.x=a0; ca.y=a1; ca.z=a2; ca.w=a3;
        char4 cb; cb.x=b0; cb.y=b1; cb.z=b2; cb.w=b3;
        *reinterpret_cast<char4*>(Qa + (size_t)row * W + j) = ca;
        *reinterpret_cast<char4*>(Qb + (size_t)row * W + j) = cb;
    }
}

// ---------------- float4 copy into wider tensor ----------------
__global__ void copy4_k(const float* __restrict__ src, int w,
                        float* __restrict__ dst, int W, int coff)
{
    int idx = blockIdx.x * 256 + threadIdx.x;
    int e = idx * 4;
    int b = e / w, j = e - b * w;
    float4 v = *reinterpret_cast<const float4*>(src + e);
    *reinterpret_cast<float4*>(dst + (size_t)b * W + coff + j) = v;
}

// ---------------- GRU gates (Keras reset_after, [z,r,h]) ----------------
__global__ void gru_gate_k(const float* __restrict__ gi, const float* __restrict__ gh,
                           const float* __restrict__ h,
                           float* __restrict__ outdet, float* __restrict__ detf,
                           float* __restrict__ xqf)
{
    const int idx = blockIdx.x * 256 + threadIdx.x;   // over B_*D_/2
    const int e = idx * 2;
    const int b = e >> 11;
    const int j = e & (D_ - 1);
    const float* gib = gi + (size_t)b * 3 * D_;
    const float* ghb = gh + (size_t)b * 3 * D_;
    float2 giz = *reinterpret_cast<const float2*>(gib + j);
    float2 gir = *reinterpret_cast<const float2*>(gib + D_ + j);
    float2 gih = *reinterpret_cast<const float2*>(gib + 2 * D_ + j);
    float2 ghz = *reinterpret_cast<const float2*>(ghb + j);
    float2 ghr = *reinterpret_cast<const float2*>(ghb + D_ + j);
    float2 ghh = *reinterpret_cast<const float2*>(ghb + 2 * D_ + j);
    float2 hv  = *reinterpret_cast<const float2*>(h + e);
    float z0 = sigmoidf_(giz.x + ghz.x), z1 = sigmoidf_(giz.y + ghz.y);
    float r0 = sigmoidf_(gir.x + ghr.x), r1 = sigmoidf_(gir.y + ghr.y);
    float n0 = tanhf(gih.x + r0 * ghh.x), n1 = tanhf(gih.y + r1 * ghh.y);
    float2 o;
    o.x = z0 * hv.x + (1.0f - z0) * n0;
    o.y = z1 * hv.y + (1.0f - z1) * n1;
    *reinterpret_cast<float2*>(detf + e) = o;
    if (outdet) *reinterpret_cast<float2*>(outdet + (size_t)b * OUTW + j) = o;
    if (xqf)    *reinterpret_cast<float2*>(xqf + (size_t)b * 4096 + j) = o;
}

// ---------------- sample = mu + std * eps ----------------
__global__ void sample_k(float* __restrict__ out, int off_mu, int off_std, int off_s,
                         const float* __restrict__ eps)
{
    const int idx = blockIdx.x * 256 + threadIdx.x;
    const int e = idx * 2;
    const int b = e >> 10;
    const int j = e & (S_ - 1);
    float* row = out + (size_t)b * OUTW;
    float2 mu = *reinterpret_cast<const float2*>(row + off_mu + j);
    float2 sd = *reinterpret_cast<const float2*>(row + off_std + j);
    float2 ep = *reinterpret_cast<const float2*>(eps + e);
    float2 o; o.x = mu.x + sd.x * ep.x; o.y = mu.y + sd.y * ep.y;
    *reinterpret_cast<float2*>(row + off_s + j) = o;
}

// ---------------- launch ----------------
extern "C" void kernel_launch(void* const* d_in, const int* in_sizes, int n_in,
                              void* d_out, int out_size)
{
    const float* obs         = (const float*)d_in[0];
    const float* context     = (const float*)d_in[1];
    const float* prev_sample = (const float*)d_in[2];
    const float* prev_h      = (const float*)d_in[3];
    const float* eps_prior   = (const float*)d_in[5];
    const float* eps_post    = (const float*)d_in[6];
    const float* W_p1  = (const float*)d_in[7];
    const float* b_p1  = (const float*)d_in[8];
    const float* Wi    = (const float*)d_in[9];
    const float* Wh    = (const float*)d_in[10];
    const float* bi    = (const float*)d_in[11];
    const float* bh    = (const float*)d_in[12];
    const float* W_p2  = (const float*)d_in[13];
    const float* b_p2  = (const float*)d_in[14];
    const float* W_pmu = (const float*)d_in[15];
    const float* b_pmu = (const float*)d_in[16];
    const float* W_pstd= (const float*)d_in[17];
    const float* b_pstd= (const float*)d_in[18];
    const float* W_q1  = (const float*)d_in[19];
    const float* b_q1  = (const float*)d_in[20];
    const float* W_q2  = (const float*)d_in[21];
    const float* b_q2  = (const float*)d_in[22];
    const float* W_qmu = (const float*)d_in[23];
    const float* b_qmu = (const float*)d_in[24];
    const float* W_qstd= (const float*)d_in[25];
    const float* b_qstd= (const float*)d_in[26];
    float* out = (float*)d_out;

    static cudaStream_t s1 = nullptr, s2 = nullptr;
    static cudaEvent_t evRoot, evWi, evGh, evGru, evQ1, evQ2, evC, evP2, evPrior;
    if (!s1) {
        cudaStreamCreateWithFlags(&s1, cudaStreamNonBlocking);
        cudaStreamCreateWithFlags(&s2, cudaStreamNonBlocking);
        cudaEventCreateWithFlags(&evRoot,  cudaEventDisableTiming);
        cudaEventCreateWithFlags(&evWi,    cudaEventDisableTiming);
        cudaEventCreateWithFlags(&evGh,    cudaEventDisableTiming);
        cudaEventCreateWithFlags(&evGru,   cudaEventDisableTiming);
        cudaEventCreateWithFlags(&evQ1,    cudaEventDisableTiming);
        cudaEventCreateWithFlags(&evQ2,    cudaEventDisableTiming);
        cudaEventCreateWithFlags(&evC,     cudaEventDisableTiming);
        cudaEventCreateWithFlags(&evP2,    cudaEventDisableTiming);
        cudaEventCreateWithFlags(&evPrior, cudaEventDisableTiming);
    }
    cudaFuncSetAttribute(gemm_imma, cudaFuncAttributeMaxDynamicSharedMemorySize, SMEMB);

#define SYMF(p, s) float* p; cudaGetSymbolAddress((void**)&p, s)
#define SYMC(p, s) signed char* p; cudaGetSymbolAddress((void**)&p, s)
    SYMC(Wp1a,g_Wp1a); SYMC(Wp1b,g_Wp1b); SYMC(Wia,g_Wia); SYMC(Wib,g_Wib);
    SYMC(Wha,g_Wha); SYMC(Whb,g_Whb); SYMC(Wp2a,g_Wp2a); SYMC(Wp2b,g_Wp2b);
    SYMC(Wcpa,g_Wcpa); SYMC(Wcpb,g_Wcpb); SYMC(Wq1a,g_Wq1a); SYMC(Wq1b,g_Wq1b);
    SYMC(Wq2a,g_Wq2a); SYMC(Wq2b,g_Wq2b); SYMC(Wcqa,g_Wcqa); SYMC(Wcqb,g_Wcqb);
    SYMF(sWp1,g_sWp1); SYMF(sWi,g_sWi); SYMF(sWh,g_sWh); SYMF(sWp2,g_sWp2);
    SYMF(sWcp,g_sWcp); SYMF(sWq1,g_sWq1); SYMF(sWq2,g_sWq2); SYMF(sWcq,g_sWcq);
    SYMC(Xa,g_Xa); SYMC(Xb,g_Xb); SYMC(Pa,g_Pa); SYMC(Pb,g_Pb);
    SYMC(h1a,g_h1a); SYMC(h1b,g_h1b); SYMC(dta,g_dta); SYMC(dtb,g_dtb);
    SYMC(h2a,g_h2a); SYMC(h2b,g_h2b); SYMC(h2qa,g_h2qa); SYMC(h2qb,g_h2qb);
    SYMC(Xqa,g_Xqa); SYMC(Xqb,g_Xqb); SYMC(dqa,g_dqa); SYMC(dqb,g_dqb);
    SYMF(sX,g_sX); SYMF(sP,g_sP); SYMF(sh1,g_sh1); SYMF(sdt,g_sdt);
    SYMF(sh2,g_sh2); SYMF(sh2q,g_sh2q); SYMF(sXq,g_sXq); SYMF(sdq,g_sdq);
    SYMF(giF,g_gi); SYMF(ghF,g_gh); SYMF(Xf,g_Xf); SYMF(Xqf,g_Xqf);
    SYMF(h1f,g_h1f); SYMF(h2f,g_h2f); SYMF(h2qf,g_h2qf);
    SYMF(detf,g_detf); SYMF(dqf,g_dqf);
    SYMF(bcp,g_bcp); SYMF(ccp,g_ccp); SYMF(bcq,g_bcq); SYMF(ccq,g_ccq);
#undef SYMF
#undef SYMC

    const dim3 tb(32, 8);

    cudaEventRecord(evRoot, 0);
    cudaStreamWaitEvent(s1, evRoot, 0);
    cudaStreamWaitEvent(s2, evRoot, 0);

    // ---- s0: p1 prep ----
    copy4_k<<<1024, 256, 0, 0>>>(prev_sample, 1024, Xf, 2048, 0);
    copy4_k<<<1024, 256, 0, 0>>>(context,     1024, Xf, 2048, 1024);
    colmax_k<<<8, 256, 0, 0>>>(W_p1, 2048, 2048, sWp1, 0);
    transpose_quant<<<dim3(64, 32), tb, 0, 0>>>(W_p1, 2048, 2048, Wp1a, Wp1b, sWp1, 2048, 0);
    quant_rows<<<1024, 256, 0, 0>>>(Xf, 2048, Xa, Xb, sX);

    // ---- s1: gh path ----
    quant_rows<<<1024, 256, 0, s1>>>(prev_h, 2048, Pa, Pb, sP);
    colmax_k<<<24, 256, 0, s1>>>(Wh, 2048, 6144, sWh, 0);
    transpose_quant<<<dim3(192, 32), tb, 0, s1>>>(Wh, 2048, 6144, Wha, Whb, sWh, 2048, 0);
    gemm_imma<<<dim3(96, 8), 256, SMEMB, s1>>>(Pa, Pb, Wha, Whb, sP, sWh, bh, nullptr,
        ghF, 2048, 6144, 0);
    cudaEventRecord(evGh, s1);

    // ---- s2: remaining weight prep ----
    colmax_k<<<24, 256, 0, s2>>>(Wi, 2048, 6144, sWi, 0);
    transpose_quant<<<dim3(192, 32), tb, 0, s2>>>(Wi, 2048, 6144, Wia, Wib, sWi, 2048, 0);
    cudaEventRecord(evWi, s2);
    copy4_k<<<2048, 256, 0, s2>>>(obs, 2048, Xqf, 4096, 2048);
    colmax_k<<<8, 256, 0, s2>>>(W_q1, 4096, 2048, sWq1, 0);
    transpose_quant<<<dim3(64, 64), tb, 0, s2>>>(W_q1, 4096, 2048, Wq1a, Wq1b, sWq1, 4096, 0);
    cudaEventRecord(evQ1, s2);
    colmax_k<<<8, 256, 0, s2>>>(W_q2, 2048, 2048, sWq2, 0);
    transpose_quant<<<dim3(64, 32), tb, 0, s2>>>(W_q2, 2048, 2048, Wq2a, Wq2b, sWq2, 2048, 0);
    cudaEventRecord(evQ2, s2);
    colmax_k<<<4, 256, 0, s2>>>(W_qmu, 2048, 1024, sWcq, 0);
    colmax_k<<<4, 256, 0, s2>>>(W_qstd, 2048, 1024, sWcq, 1024);
    transpose_quant<<<dim3(32, 32), tb, 0, s2>>>(W_qmu, 2048, 1024, Wcqa, Wcqb, sWcq, 2048, 0);
    transpose_quant<<<dim3(32, 32), tb, 0, s2>>>(W_qstd, 2048, 1024, Wcqa, Wcqb, sWcq, 2048, 1024);
    colprep_q<<<2048, 256, 0, s2>>>(b_qmu, b_qstd, Wcqa, Wcqb, sWcq, 2048, bcq, ccq);
    cudaEventRecord(evC, s2);
    colmax_k<<<8, 256, 0, s2>>>(W_p2, 2048, 2048, sWp2, 0);
    transpose_quant<<<dim3(64, 32), tb, 0, s2>>>(W_p2, 2048, 2048, Wp2a, Wp2b, sWp2, 2048, 0);
    colmax_k<<<4, 256, 0, s2>>>(W_pmu, 2048, 1024, sWcp, 0);
    colmax_k<<<4, 256, 0, s2>>>(W_pstd, 2048, 1024, sWcp, 1024);
    transpose_quant<<<dim3(32, 32), tb, 0, s2>>>(W_pmu, 2048, 1024, Wcpa, Wcpb, sWcp, 2048, 0);
    transpose_quant<<<dim3(32, 32), tb, 0, s2>>>(W_pstd, 2048, 1024, Wcpa, Wcpb, sWcp, 2048, 1024);
    colprep_q<<<2048, 256, 0, s2>>>(b_pmu, b_pstd, Wcpa, Wcpb, sWcp, 2048, bcp, ccp);
    cudaEventRecord(evP2, s2);

    // ---- s0: prior chain ----
    gemm_imma<<<dim3(32, 8), 256, SMEMB, 0>>>(Xa, Xb, Wp1a, Wp1b, sX, sWp1, b_p1, nullptr,
        h1f, 2048, 2048, 1);
    quant_rows<<<1024, 256, 0, 0>>>(h1f, 2048, h1a, h1b, sh1);
    cudaStreamWaitEvent(0, evWi, 0);
    gemm_imma<<<dim3(96, 8), 256, SMEMB, 0>>>(h1a, h1b, Wia, Wib, sh1, sWi, bi, nullptr,
        giF, 2048, 6144, 0);
    cudaStreamWaitEvent(0, evGh, 0);
    gru_gate_k<<<(B_ * D_) / 512, 256, 0, 0>>>(giF, ghF, prev_h, out + 3 * S_, detf, Xqf);
    cudaEventRecord(evGru, 0);

    // ---- s1: prior tail ----
    cudaStreamWaitEvent(s1, evGru, 0);
    cudaStreamWaitEvent(s1, evP2, 0);
    quant_rows<<<1024, 256, 0, s1>>>(detf, 2048, dta, dtb, sdt);
    gemm_imma<<<dim3(32, 8), 256, SMEMB, s1>>>(dta, dtb, Wp2a, Wp2b, sdt, sWp2, b_p2, nullptr,
        h2f, 2048, 2048, 1);
    quant_rows<<<1024, 256, 0, s1>>>(h2f, 2048, h2a, h2b, sh2);
    gemm_imma<<<dim3(32, 8), 256, SMEMB, s1>>>(h2a, h2b, Wcpa, Wcpb, sh2, sWcp, bcp, ccp,
        out, 2048, OUTW, 2);
    sample_k<<<(B_ * S_) / 512, 256, 0, s1>>>(out, 0, S_, 2 * S_, eps_prior);
    cudaEventRecord(evPrior, s1);

    // ---- s0: posterior chain ----
    cudaStreamWaitEvent(0, evQ1, 0);
    quant_rows<<<1024, 256, 0, 0>>>(Xqf, 4096, Xqa, Xqb, sXq);
    gemm_imma<<<dim3(32, 8), 256, SMEMB, 0>>>(Xqa, Xqb, Wq1a, Wq1b, sXq, sWq1, b_q1, nullptr,
        h1f, 4096, 2048, 1);
    quant_rows<<<1024, 256, 0, 0>>>(h1f, 2048, h1a, h1b, sh1);
    gemm_imma<<<dim3(96, 8), 256, SMEMB, 0>>>(h1a, h1b, Wia, Wib, sh1, sWi, bi, nullptr,
        giF, 2048, 6144, 0);
    gru_gate_k<<<(B_ * D_) / 512, 256, 0, 0>>>(giF, ghF, prev_h, nullptr, dqf, nullptr);
    quant_rows<<<1024, 256, 0, 0>>>(dqf, 2048, dqa, dqb, sdq);
    cudaStreamWaitEvent(0, evQ2, 0);
    gemm_imma<<<dim3(32, 8), 256, SMEMB, 0>>>(dqa, dqb, Wq2a, Wq2b, sdq, sWq2, b_q2, nullptr,
        h2qf, 2048, 2048, 1);
    quant_rows<<<1024, 256, 0, 0>>>(h2qf, 2048, h2qa, h2qb, sh2q);
    cudaStreamWaitEvent(0, evC, 0);
    gemm_imma<<<dim3(32, 8), 256, SMEMB, 0>>>(h2qa, h2qb, Wcqa, Wcqb, sh2q, sWcq, bcq, ccq,
        out + 5 * S_, 2048, OUTW, 2);
    sample_k<<<(B_ * S_) / 512, 256, 0, 0>>>(out, 5 * S_, 6 * S_, 7 * S_, eps_post);

    cudaStreamWaitEvent(0, evPrior, 0);

    (void)in_sizes; (void)n_in; (void)out_size;
}

// round 8
// speedup vs baseline: 2.5117x; 2.5117x over previous
#include <cuda_runtime.h>
#include <cuda_bf16.h>
#include <math.h>
#include <stdint.h>

#define B_   1024
#define S_   1024
#define D_   2048
#define E_   2048
#define OUTW 8192

#define TM 128
#define KC 32
#define NSTAGE 3

// ---------------- device scratch ----------------
__device__ __align__(128) __nv_bfloat16 g_Wp1h[2048u*2048u], g_Wp1l[2048u*2048u];
__device__ __align__(128) __nv_bfloat16 g_Wih [6144u*2048u], g_Wil [6144u*2048u];
__device__ __align__(128) __nv_bfloat16 g_Whh [6144u*2048u], g_Whl [6144u*2048u];
__device__ __align__(128) __nv_bfloat16 g_Wp2h[2048u*2048u], g_Wp2l[2048u*2048u];
__device__ __align__(128) __nv_bfloat16 g_Wcph[2048u*2048u], g_Wcpl[2048u*2048u];
__device__ __align__(128) __nv_bfloat16 g_Wq1h[2048u*4096u], g_Wq1l[2048u*4096u];
__device__ __align__(128) __nv_bfloat16 g_Wq2h[2048u*2048u], g_Wq2l[2048u*2048u];
__device__ __align__(128) __nv_bfloat16 g_Wcqh[2048u*2048u], g_Wcql[2048u*2048u];
__device__ __align__(128) __nv_bfloat16 g_Xh [B_*2048u], g_Xl [B_*2048u];
__device__ __align__(128) __nv_bfloat16 g_Ph [B_*2048u], g_Pl [B_*2048u];
__device__ __align__(128) __nv_bfloat16 g_h1h[B_*2048u], g_h1l[B_*2048u];
__device__ __align__(128) __nv_bfloat16 g_dth[B_*2048u], g_dtl[B_*2048u];
__device__ __align__(128) __nv_bfloat16 g_h2h[B_*2048u], g_h2l[B_*2048u];
__device__ __align__(128) __nv_bfloat16 g_h2qh[B_*2048u], g_h2ql[B_*2048u];
__device__ __align__(128) __nv_bfloat16 g_Xqh[B_*4096u], g_Xql[B_*4096u];
__device__ __align__(128) __nv_bfloat16 g_dqh[B_*2048u], g_dql[B_*2048u];
__device__ __align__(128) float g_gi[B_*6144u];
__device__ __align__(128) float g_gh[B_*6144u];
__device__ __align__(128) float g_bcp[2048], g_ccp[2048], g_bcq[2048], g_ccq[2048];

// ---------------- helpers ----------------
__device__ __forceinline__ float sigmoidf_(float x) { return 1.0f / (1.0f + expf(-x)); }
__device__ __forceinline__ float softplusf_(float x) {
    return fmaxf(x, 0.0f) + log1pf(expf(-fabsf(x)));
}
__device__ __forceinline__ void split2(float v, __nv_bfloat16& h, __nv_bfloat16& l) {
    h = __float2bfloat16(v);
    l = __float2bfloat16(v - __bfloat162float(h));
}
__device__ __forceinline__ uint32_t smem_u32(const void* p) {
    uint32_t a;
    asm("{ .reg .u64 t; cvta.to.shared.u64 t, %1; cvt.u32.u64 %0, t; }" : "=r"(a) : "l"(p));
    return a;
}
__device__ __forceinline__ void cp16(uint32_t s, const void* g) {
    asm volatile("cp.async.cg.shared.global [%0], [%1], 16;" :: "r"(s), "l"(g));
}
__device__ __forceinline__ void cpcommit() { asm volatile("cp.async.commit_group;" ::: "memory"); }
__device__ __forceinline__ void cpwait1() { asm volatile("cp.async.wait_group 1;" ::: "memory"); }
__device__ __forceinline__ void cpwait0() { asm volatile("cp.async.wait_group 0;" ::: "memory"); }
__device__ __forceinline__ void ldm_x4(uint32_t* r, uint32_t addr) {
    asm volatile("ldmatrix.sync.aligned.m8n8.x4.shared.b16 {%0,%1,%2,%3}, [%4];"
                 : "=r"(r[0]), "=r"(r[1]), "=r"(r[2]), "=r"(r[3]) : "r"(addr));
}
__device__ __forceinline__ void mma_bf16(float* c, const uint32_t* a, const uint32_t* b) {
    asm volatile(
        "mma.sync.aligned.m16n8k16.row.col.f32.bf16.bf16.f32 "
        "{%0,%1,%2,%3}, {%4,%5,%6,%7}, {%8,%9}, {%0,%1,%2,%3};"
        : "+f"(c[0]), "+f"(c[1]), "+f"(c[2]), "+f"(c[3])
        : "r"(a[0]), "r"(a[1]), "r"(a[2]), "r"(a[3]), "r"(b[0]), "r"(b[1]));
}
__device__ __forceinline__ uint32_t tadr(uint32_t base, int row, int kc) {
    return base + (uint32_t)(row * 64) + (uint32_t)((kc ^ ((row >> 1) & 3)) << 4);
}

// ---------------- templated split-bf16 HMMA GEMM ----------------
template<int TNP>
__global__ void __launch_bounds__(256) gemm_mma(
    const __nv_bfloat16* __restrict__ Ah, const __nv_bfloat16* __restrict__ Al,
    const __nv_bfloat16* __restrict__ Bh, const __nv_bfloat16* __restrict__ Bl,
    const float* __restrict__ bias, const float* __restrict__ csum,
    float* __restrict__ Cf, __nv_bfloat16* __restrict__ Chi, __nv_bfloat16* __restrict__ Clo,
    int K, int ldc, int epi)
{
    constexpr int BNF   = TNP / 32;
    constexpr int NHALF = TNP / 64;
    constexpr uint32_t ATILE = 128 * 64;
    constexpr uint32_t BTILE = (uint32_t)TNP * 64;
    constexpr uint32_t SB_H  = 2 * ATILE;
    constexpr uint32_t SB_L  = 2 * ATILE + BTILE;
    constexpr uint32_t STG   = 2 * ATILE + 2 * BTILE;

    extern __shared__ __align__(1024) char smem[];
    const uint32_t sb = smem_u32(smem);
    const int tid = threadIdx.x;
    const int lane = tid & 31, wid = tid >> 5;
    const int wr = wid >> 2, wc = wid & 3;
    const int bm = blockIdx.y * TM;
    const int bn = blockIdx.x * TNP;
    const int g = lane >> 3, i8 = lane & 7;

    float acc[4][BNF][4];
#pragma unroll
    for (int a = 0; a < 4; a++)
#pragma unroll
        for (int b = 0; b < BNF; b++)
#pragma unroll
            for (int k = 0; k < 4; k++) acc[a][b][k] = 0.0f;

    auto load_stage = [&](uint32_t sbase, int kpos) {
#pragma unroll
        for (int q = tid; q < 512; q += 256) {
            int row = q >> 2, kc = q & 3;
            uint32_t so = tadr(0, row, kc);
            size_t go = (size_t)(bm + row) * K + kpos + kc * 8;
            cp16(sbase + so, Ah + go);
            cp16(sbase + ATILE + so, Al + go);
        }
#pragma unroll
        for (int q = tid; q < TNP * 4; q += 256) {
            int row = q >> 2, kc = q & 3;
            uint32_t so = tadr(0, row, kc);
            size_t go = (size_t)(bn + row) * K + kpos + kc * 8;
            cp16(sbase + SB_H + so, Bh + go);
            cp16(sbase + SB_L + so, Bl + go);
        }
        cpcommit();
    };

    load_stage(sb, 0);
    load_stage(sb + STG, KC);

    const int nk = K / KC;
    const int aRowBase = wr * 64 + (g & 1) * 8 + i8;
    const int aKsel = g >> 1;
    const int bRowBase = wc * (TNP / 4) + (g >> 1) * 8 + i8;
    const int bKsel = g & 1;

    int bufc = 0, bufl = 2;
    for (int s = 0; s < nk; s++) {
        if (s < nk - 1) cpwait1(); else cpwait0();
        __syncthreads();
        if (s + 2 < nk) load_stage(sb + (uint32_t)bufl * STG, (s + 2) * KC);

        const uint32_t base = sb + (uint32_t)bufc * STG;
        const uint32_t bAh = base, bAl = base + ATILE;
        const uint32_t bBh = base + SB_H, bBl = base + SB_L;

#pragma unroll
        for (int step = 0; step < 2; step++) {
            const int c0 = step * 2;
            uint32_t Bfh[BNF][2], Bfl[BNF][2];
#pragma unroll
            for (int half = 0; half < NHALF; half++) {
                uint32_t r[4];
                int nrow = bRowBase + half * 16;
                int kc = c0 + bKsel;
                ldm_x4(r, tadr(bBh, nrow, kc));
                Bfh[half * 2 + 0][0] = r[0]; Bfh[half * 2 + 0][1] = r[1];
                Bfh[half * 2 + 1][0] = r[2]; Bfh[half * 2 + 1][1] = r[3];
                ldm_x4(r, tadr(bBl, nrow, kc));
                Bfl[half * 2 + 0][0] = r[0]; Bfl[half * 2 + 0][1] = r[1];
                Bfl[half * 2 + 1][0] = r[2]; Bfl[half * 2 + 1][1] = r[3];
            }
#pragma unroll
            for (int am = 0; am < 4; am++) {
                uint32_t Afh[4], Afl[4];
                int arow = aRowBase + am * 16;
                int kc = c0 + aKsel;
                ldm_x4(Afh, tadr(bAh, arow, kc));
                ldm_x4(Afl, tadr(bAl, arow, kc));
#pragma unroll
                for (int bnf = 0; bnf < BNF; bnf++) mma_bf16(acc[am][bnf], Afh, Bfh[bnf]);
#pragma unroll
                for (int bnf = 0; bnf < BNF; bnf++) mma_bf16(acc[am][bnf], Afh, Bfl[bnf]);
#pragma unroll
                for (int bnf = 0; bnf < BNF; bnf++) mma_bf16(acc[am][bnf], Afl, Bfh[bnf]);
            }
        }
        bufc = (bufc == 2) ? 0 : bufc + 1;
        bufl = (bufl == 2) ? 0 : bufl + 1;
    }

    const int rQ = lane >> 2;
    const int cP = (lane & 3) * 2;
#pragma unroll
    for (int am = 0; am < 4; am++) {
#pragma unroll
        for (int bnf = 0; bnf < BNF; bnf++) {
            const int r0 = bm + wr * 64 + am * 16 + rQ;
            const int c  = bn + wc * (TNP / 4) + bnf * 8 + cP;
            float v0 = acc[am][bnf][0] + bias[c];
            float v1 = acc[am][bnf][1] + bias[c + 1];
            float v2 = acc[am][bnf][2] + bias[c];
            float v3 = acc[am][bnf][3] + bias[c + 1];
            if (epi == 1) {
                v0 = fmaxf(v0, 0.0f); v1 = fmaxf(v1, 0.0f);
                v2 = fmaxf(v2, 0.0f); v3 = fmaxf(v3, 0.0f);
                __nv_bfloat16 h0,l0,h1,l1,h2,l2,h3,l3;
                split2(v0,h0,l0); split2(v1,h1,l1); split2(v2,h2,l2); split2(v3,h3,l3);
                __nv_bfloat162 p01; p01.x = h0; p01.y = h1;
                __nv_bfloat162 q01; q01.x = l0; q01.y = l1;
                __nv_bfloat162 p23; p23.x = h2; p23.y = h3;
                __nv_bfloat162 q23; q23.x = l2; q23.y = l3;
                *reinterpret_cast<__nv_bfloat162*>(Chi + (size_t)r0 * ldc + c) = p01;
                *reinterpret_cast<__nv_bfloat162*>(Clo + (size_t)r0 * ldc + c) = q01;
                *reinterpret_cast<__nv_bfloat162*>(Chi + (size_t)(r0 + 8) * ldc + c) = p23;
                *reinterpret_cast<__nv_bfloat162*>(Clo + (size_t)(r0 + 8) * ldc + c) = q23;
            } else {
                if (epi == 2 && c >= S_) {
                    const float cs0 = csum[c], cs1 = csum[c + 1];
                    v0 = softplusf_(v0 + cs0) + 1e-4f;
                    v1 = softplusf_(v1 + cs1) + 1e-4f;
                    v2 = softplusf_(v2 + cs0) + 1e-4f;
                    v3 = softplusf_(v3 + cs1) + 1e-4f;
                }
                float2 w01; w01.x = v0; w01.y = v1;
                float2 w23; w23.x = v2; w23.y = v3;
                *reinterpret_cast<float2*>(Cf + (size_t)r0 * ldc + c) = w01;
                *reinterpret_cast<float2*>(Cf + (size_t)(r0 + 8) * ldc + c) = w23;
            }
        }
    }
}

// ---------------- transpose + split (vectorized) ----------------
__global__ void transpose_split(const float* __restrict__ W, int K, int N,
                                __nv_bfloat16* __restrict__ Th, __nv_bfloat16* __restrict__ Tl,
                                int ldT, int roff)
{
    __shared__ float t[64][33];
    const int n0 = blockIdx.x * 32, k0 = blockIdx.y * 64;
    const int tx = threadIdx.x, ty = threadIdx.y;
#pragma unroll
    for (int r = 0; r < 64; r += 8)
        t[ty + r][tx] = W[(size_t)(k0 + ty + r) * N + n0 + tx];
    __syncthreads();
#pragma unroll
    for (int r = 0; r < 32; r += 8) {
        const int n = r + ty;
        float v0 = t[2 * tx][n], v1 = t[2 * tx + 1][n];
        __nv_bfloat16 h0, l0, h1, l1;
        split2(v0, h0, l0); split2(v1, h1, l1);
        __nv_bfloat162 H; H.x = h0; H.y = h1;
        __nv_bfloat162 L; L.x = l0; L.y = l1;
        size_t o = (size_t)(roff + n0 + n) * ldT + k0 + 2 * tx;
        *reinterpret_cast<__nv_bfloat162*>(Th + o) = H;
        *reinterpret_cast<__nv_bfloat162*>(Tl + o) = L;
    }
}

// ---------------- bias + 0.54*colsum prep ----------------
__global__ void colprep(const float* __restrict__ bmu, const float* __restrict__ bstd,
                        const __nv_bfloat16* __restrict__ Th, const __nv_bfloat16* __restrict__ Tl,
                        int K, float* __restrict__ bcat, float* __restrict__ ccat)
{
    const int n = blockIdx.x;
    if (n < S_) {
        if (threadIdx.x == 0) { bcat[n] = bmu[n]; ccat[n] = 0.0f; }
        return;
    }
    __shared__ float red[256];
    const __nv_bfloat16* rh = Th + (size_t)n * K;
    const __nv_bfloat16* rl = Tl + (size_t)n * K;
    float s = 0.0f;
    for (int k = threadIdx.x; k < K; k += 256)
        s += __bfloat162float(rh[k]) + __bfloat162float(rl[k]);
    red[threadIdx.x] = s;
    __syncthreads();
    for (int st = 128; st; st >>= 1) {
        if (threadIdx.x < st) red[threadIdx.x] += red[threadIdx.x + st];
        __syncthreads();
    }
    if (threadIdx.x == 0) { bcat[n] = bstd[n - S_]; ccat[n] = 0.54f * red[0]; }
}

// ---------------- fp32 -> split bf16, vectorized x4 ----------------
__global__ void split_convert4(const float* __restrict__ src, int srcW,
                               __nv_bfloat16* __restrict__ dh, __nv_bfloat16* __restrict__ dl,
                               int dstW, int coff)
{
    int idx = blockIdx.x * 256 + threadIdx.x;
    int e = idx * 4;
    int b = e / srcW, j = e - b * srcW;
    float4 v = *reinterpret_cast<const float4*>(src + e);
    __nv_bfloat16 h0,l0,h1,l1,h2,l2,h3,l3;
    split2(v.x,h0,l0); split2(v.y,h1,l1); split2(v.z,h2,l2); split2(v.w,h3,l3);
    __nv_bfloat162 H0; H0.x=h0; H0.y=h1;
    __nv_bfloat162 H1; H1.x=h2; H1.y=h3;
    __nv_bfloat162 L0; L0.x=l0; L0.y=l1;
    __nv_bfloat162 L1; L1.x=l2; L1.y=l3;
    size_t o = (size_t)b * dstW + coff + j;
    *reinterpret_cast<__nv_bfloat162*>(dh + o) = H0;
    *reinterpret_cast<__nv_bfloat162*>(dh + o + 2) = H1;
    *reinterpret_cast<__nv_bfloat162*>(dl + o) = L0;
    *reinterpret_cast<__nv_bfloat162*>(dl + o + 2) = L1;
}

// ---------------- GRU gates, vectorized x2 ----------------
__global__ void gru_gate_k(const float* __restrict__ gi, const float* __restrict__ gh,
                           const float* __restrict__ h,
                           float* __restrict__ outdet,
                           __nv_bfloat16* __restrict__ dh, __nv_bfloat16* __restrict__ dl,
                           __nv_bfloat16* __restrict__ xh, __nv_bfloat16* __restrict__ xl)
{
    const int idx = blockIdx.x * 256 + threadIdx.x;
    const int e = idx * 2;
    const int b = e >> 11;
    const int j = e & (D_ - 1);
    const float* gib = gi + (size_t)b * 3 * D_;
    const float* ghb = gh + (size_t)b * 3 * D_;
    float2 giz = *reinterpret_cast<const float2*>(gib + j);
    float2 gir = *reinterpret_cast<const float2*>(gib + D_ + j);
    float2 gih = *reinterpret_cast<const float2*>(gib + 2 * D_ + j);
    float2 ghz = *reinterpret_cast<const float2*>(ghb + j);
    float2 ghr = *reinterpret_cast<const float2*>(ghb + D_ + j);
    float2 ghh = *reinterpret_cast<const float2*>(ghb + 2 * D_ + j);
    float2 hv  = *reinterpret_cast<const float2*>(h + e);
    float z0 = sigmoidf_(giz.x + ghz.x), z1 = sigmoidf_(giz.y + ghz.y);
    float r0 = sigmoidf_(gir.x + ghr.x), r1 = sigmoidf_(gir.y + ghr.y);
    float n0 = tanhf(gih.x + r0 * ghh.x), n1 = tanhf(gih.y + r1 * ghh.y);
    float v0 = z0 * hv.x + (1.0f - z0) * n0;
    float v1 = z1 * hv.y + (1.0f - z1) * n1;
    if (outdet) {
        float2 o; o.x = v0; o.y = v1;
        *reinterpret_cast<float2*>(outdet + (size_t)b * OUTW + j) = o;
    }
    __nv_bfloat16 h0,l0,h1,l1;
    split2(v0,h0,l0); split2(v1,h1,l1);
    __nv_bfloat162 H; H.x=h0; H.y=h1;
    __nv_bfloat162 L; L.x=l0; L.y=l1;
    *reinterpret_cast<__nv_bfloat162*>(dh + e) = H;
    *reinterpret_cast<__nv_bfloat162*>(dl + e) = L;
    if (xh) {
        *reinterpret_cast<__nv_bfloat162*>(xh + (size_t)b * 4096 + j) = H;
        *reinterpret_cast<__nv_bfloat162*>(xl + (size_t)b * 4096 + j) = L;
    }
}

// ---------------- sample = mu + std * eps, vectorized x2 ----------------
__global__ void sample_k(float* __restrict__ out, int off_mu, int off_std, int off_s,
                         const float* __restrict__ eps)
{
    const int idx = blockIdx.x * 256 + threadIdx.x;
    const int e = idx * 2;
    const int b = e >> 10;
    const int j = e & (S_ - 1);
    float* row = out + (size_t)b * OUTW;
    float2 mu = *reinterpret_cast<const float2*>(row + off_mu + j);
    float2 sd = *reinterpret_cast<const float2*>(row + off_std + j);
    float2 ep = *reinterpret_cast<const float2*>(eps + e);
    float2 o; o.x = mu.x + sd.x * ep.x; o.y = mu.y + sd.y * ep.y;
    *reinterpret_cast<float2*>(row + off_s + j) = o;
}

// ---------------- launch ----------------
extern "C" void kernel_launch(void* const* d_in, const int* in_sizes, int n_in,
                              void* d_out, int out_size)
{
    const float* obs         = (const float*)d_in[0];
    const float* context     = (const float*)d_in[1];
    const float* prev_sample = (const float*)d_in[2];
    const float* prev_h      = (const float*)d_in[3];
    const float* eps_prior   = (const float*)d_in[5];
    const float* eps_post    = (const float*)d_in[6];
    const float* W_p1  = (const float*)d_in[7];
    const float* b_p1  = (const float*)d_in[8];
    const float* Wi    = (const float*)d_in[9];
    const float* Wh    = (const float*)d_in[10];
    const float* bi    = (const float*)d_in[11];
    const float* bh    = (const float*)d_in[12];
    const float* W_p2  = (const float*)d_in[13];
    const float* b_p2  = (const float*)d_in[14];
    const float* W_pmu = (const float*)d_in[15];
    const float* b_pmu = (const float*)d_in[16];
    const float* W_pstd= (const float*)d_in[17];
    const float* b_pstd= (const float*)d_in[18];
    const float* W_q1  = (const float*)d_in[19];
    const float* b_q1  = (const float*)d_in[20];
    const float* W_q2  = (const float*)d_in[21];
    const float* b_q2  = (const float*)d_in[22];
    const float* W_qmu = (const float*)d_in[23];
    const float* b_qmu = (const float*)d_in[24];
    const float* W_qstd= (const float*)d_in[25];
    const float* b_qstd= (const float*)d_in[26];
    float* out = (float*)d_out;

    static cudaStream_t s1 = nullptr, s2 = nullptr;
    static cudaEvent_t evRoot, evWi, evGh, evGru, evC, evP2, evPrior, evXq;
    if (!s1) {
        cudaStreamCreateWithFlags(&s1, cudaStreamNonBlocking);
        cudaStreamCreateWithFlags(&s2, cudaStreamNonBlocking);
        cudaEventCreateWithFlags(&evRoot,  cudaEventDisableTiming);
        cudaEventCreateWithFlags(&evWi,    cudaEventDisableTiming);
        cudaEventCreateWithFlags(&evGh,    cudaEventDisableTiming);
        cudaEventCreateWithFlags(&evGru,   cudaEventDisableTiming);
        cudaEventCreateWithFlags(&evC,     cudaEventDisableTiming);
        cudaEventCreateWithFlags(&evP2,    cudaEventDisableTiming);
        cudaEventCreateWithFlags(&evPrior, cudaEventDisableTiming);
        cudaEventCreateWithFlags(&evXq,    cudaEventDisableTiming);
    }
    constexpr int SMEM128 = NSTAGE * (2 * 128 * 64 + 2 * 128 * 64);   // 96KB
    constexpr int SMEM256 = NSTAGE * (2 * 128 * 64 + 2 * 256 * 64);   // 144KB
    cudaFuncSetAttribute(gemm_mma<128>, cudaFuncAttributeMaxDynamicSharedMemorySize, SMEM128);
    cudaFuncSetAttribute(gemm_mma<256>, cudaFuncAttributeMaxDynamicSharedMemorySize, SMEM256);

#define SYM(p, s) float* p; cudaGetSymbolAddress((void**)&p, s)
#define SYMB(p, s) __nv_bfloat16* p; cudaGetSymbolAddress((void**)&p, s)
    SYMB(Wp1h,g_Wp1h); SYMB(Wp1l,g_Wp1l); SYMB(Wih,g_Wih); SYMB(Wil,g_Wil);
    SYMB(Whh,g_Whh); SYMB(Whl,g_Whl); SYMB(Wp2h,g_Wp2h); SYMB(Wp2l,g_Wp2l);
    SYMB(Wcph,g_Wcph); SYMB(Wcpl,g_Wcpl); SYMB(Wq1h,g_Wq1h); SYMB(Wq1l,g_Wq1l);
    SYMB(Wq2h,g_Wq2h); SYMB(Wq2l,g_Wq2l); SYMB(Wcqh,g_Wcqh); SYMB(Wcql,g_Wcql);
    SYMB(Xh,g_Xh); SYMB(Xl,g_Xl); SYMB(Ph,g_Ph); SYMB(Pl,g_Pl);
    SYMB(h1h,g_h1h); SYMB(h1l,g_h1l); SYMB(dth,g_dth); SYMB(dtl,g_dtl);
    SYMB(h2h,g_h2h); SYMB(h2l,g_h2l); SYMB(h2qh,g_h2qh); SYMB(h2ql,g_h2ql);
    SYMB(Xqh,g_Xqh); SYMB(Xql,g_Xql); SYMB(dqh,g_dqh); SYMB(dql,g_dql);
    SYM(giF,g_gi); SYM(ghF,g_gh);
    SYM(bcp,g_bcp); SYM(ccp,g_ccp); SYM(bcq,g_bcq); SYM(ccq,g_ccq);
#undef SYM
#undef SYMB

    const dim3 tb(32, 8);

    cudaEventRecord(evRoot, 0);
    cudaStreamWaitEvent(s1, evRoot, 0);
    cudaStreamWaitEvent(s2, evRoot, 0);

    // ---- s0: p1 prep + p1 GEMM (p1 GEMM = 4th kernel launch, for ncu capture) ----
    split_convert4<<<1024, 256, 0, 0>>>(prev_sample, 1024, Xh, Xl, 2048, 0);   // #1
    split_convert4<<<1024, 256, 0, 0>>>(context,     1024, Xh, Xl, 2048, 1024);// #2
    transpose_split<<<dim3(64, 32), tb, 0, 0>>>(W_p1, 2048, 2048, Wp1h, Wp1l, 2048, 0); // #3
    gemm_mma<128><<<dim3(16, 8), 256, SMEM128, 0>>>(Xh, Xl, Wp1h, Wp1l, b_p1, nullptr,
        nullptr, h1h, h1l, 2048, 2048, 1);                                     // #4 <- ncu
    // ---- s1: GRU-h prep + gh GEMM ----
    split_convert4<<<2048, 256, 0, s1>>>(prev_h, 2048, Ph, Pl, 2048, 0);
    transpose_split<<<dim3(192, 32), tb, 0, s1>>>(Wh, 2048, 6144, Whh, Whl, 2048, 0);
    gemm_mma<256><<<dim3(24, 8), 256, SMEM256, s1>>>(Ph, Pl, Whh, Whl, bh, nullptr,
        ghF, nullptr, nullptr, 2048, 6144, 0);
    cudaEventRecord(evGh, s1);

    // ---- s2: remaining prep ----
    transpose_split<<<dim3(192, 32), tb, 0, s2>>>(Wi, 2048, 6144, Wih, Wil, 2048, 0);
    cudaEventRecord(evWi, s2);
    split_convert4<<<2048, 256, 0, s2>>>(obs, 2048, Xqh, Xql, 4096, 2048);
    cudaEventRecord(evXq, s2);
    transpose_split<<<dim3(64, 64), tb, 0, s2>>>(W_q1, 4096, 2048, Wq1h, Wq1l, 4096, 0);
    transpose_split<<<dim3(64, 32), tb, 0, s2>>>(W_q2, 2048, 2048, Wq2h, Wq2l, 2048, 0);
    transpose_split<<<dim3(32, 32), tb, 0, s2>>>(W_qmu, 2048, 1024, Wcqh, Wcql, 2048, 0);
    transpose_split<<<dim3(32, 32), tb, 0, s2>>>(W_qstd,2048, 1024, Wcqh, Wcql, 2048, 1024);
    colprep<<<2048, 256, 0, s2>>>(b_qmu, b_qstd, Wcqh, Wcql, 2048, bcq, ccq);
    cudaEventRecord(evC, s2);
    transpose_split<<<dim3(64, 32), tb, 0, s2>>>(W_p2, 2048, 2048, Wp2h, Wp2l, 2048, 0);
    transpose_split<<<dim3(32, 32), tb, 0, s2>>>(W_pmu, 2048, 1024, Wcph, Wcpl, 2048, 0);
    transpose_split<<<dim3(32, 32), tb, 0, s2>>>(W_pstd,2048, 1024, Wcph, Wcpl, 2048, 1024);
    colprep<<<2048, 256, 0, s2>>>(b_pmu, b_pstd, Wcph, Wcpl, 2048, bcp, ccp);
    cudaEventRecord(evP2, s2);

    // ---- s0: prior chain continues ----
    cudaStreamWaitEvent(0, evWi, 0);
    gemm_mma<256><<<dim3(24, 8), 256, SMEM256, 0>>>(h1h, h1l, Wih, Wil, bi, nullptr,
        giF, nullptr, nullptr, 2048, 6144, 0);
    cudaStreamWaitEvent(0, evGh, 0);
    cudaStreamWaitEvent(0, evXq, 0);   // gru writes into Xqh/Xql alongside obs columns
    gru_gate_k<<<(B_ * D_) / 512, 256, 0, 0>>>(giF, ghF, prev_h, out + 3 * S_, dth, dtl, Xqh, Xql);
    cudaEventRecord(evGru, 0);

    // ---- s1: prior tail ----
    cudaStreamWaitEvent(s1, evGru, 0);
    cudaStreamWaitEvent(s1, evP2, 0);
    gemm_mma<128><<<dim3(16, 8), 256, SMEM128, s1>>>(dth, dtl, Wp2h, Wp2l, b_p2, nullptr,
        nullptr, h2h, h2l, 2048, 2048, 1);
    gemm_mma<128><<<dim3(16, 8), 256, SMEM128, s1>>>(h2h, h2l, Wcph, Wcpl, bcp, ccp,
        out, nullptr, nullptr, 2048, OUTW, 2);
    sample_k<<<(B_ * S_) / 512, 256, 0, s1>>>(out, 0, S_, 2 * S_, eps_prior);
    cudaEventRecord(evPrior, s1);

    // ---- s0: posterior chain ----
    cudaStreamWaitEvent(0, evC, 0);
    gemm_mma<128><<<dim3(16, 8), 256, SMEM128, 0>>>(Xqh, Xql, Wq1h, Wq1l, b_q1, nullptr,
        nullptr, h1h, h1l, 4096, 2048, 1);
    gemm_mma<256><<<dim3(24, 8), 256, SMEM256, 0>>>(h1h, h1l, Wih, Wil, bi, nullptr,
        giF, nullptr, nullptr, 2048, 6144, 0);
    gru_gate_k<<<(B_ * D_) / 512, 256, 0, 0>>>(giF, ghF, prev_h, nullptr, dqh, dql, nullptr, nullptr);
    gemm_mma<128><<<dim3(16, 8), 256, SMEM128, 0>>>(dqh, dql, Wq2h, Wq2l, b_q2, nullptr,
        nullptr, h2qh, h2ql, 2048, 2048, 1);
    gemm_mma<128><<<dim3(16, 8), 256, SMEM128, 0>>>(h2qh, h2ql, Wcqh, Wcql, bcq, ccq,
        out + 5 * S_, nullptr, nullptr, 2048, OUTW, 2);
    sample_k<<<(B_ * S_) / 512, 256, 0, 0>>>(out, 5 * S_, 6 * S_, 7 * S_, eps_post);

    cudaStreamWaitEvent(0, evPrior, 0);

    (void)in_sizes; (void)n_in; (void)out_size;
}

// round 9
// speedup vs baseline: 2.7393x; 1.0906x over previous
#include <cuda_runtime.h>
#include <cuda_bf16.h>
#include <math.h>
#include <stdint.h>

#define B_   1024
#define S_   1024
#define D_   2048
#define E_   2048
#define OUTW 8192

#define TM 128
#define TN 64
#define KC 32
#define NSTAGE 3
// stage: A_hi 8KB + A_lo 8KB + B_hi 4KB + B_lo 4KB = 24KB
#define ATILE 8192u
#define BTILE 4096u
#define SB_H  (2u * ATILE)
#define SB_L  (2u * ATILE + BTILE)
#define STG   (2u * ATILE + 2u * BTILE)
#define SMEMB ((int)(NSTAGE * STG))

// ---------------- device scratch ----------------
__device__ __align__(128) __nv_bfloat16 g_Wp1h[2048u*2048u], g_Wp1l[2048u*2048u];
__device__ __align__(128) __nv_bfloat16 g_Wih [6144u*2048u], g_Wil [6144u*2048u];
__device__ __align__(128) __nv_bfloat16 g_Whh [6144u*2048u], g_Whl [6144u*2048u];
__device__ __align__(128) __nv_bfloat16 g_Wp2h[2048u*2048u], g_Wp2l[2048u*2048u];
__device__ __align__(128) __nv_bfloat16 g_Wcph[2048u*2048u], g_Wcpl[2048u*2048u];
__device__ __align__(128) __nv_bfloat16 g_Wq1h[2048u*4096u], g_Wq1l[2048u*4096u];
__device__ __align__(128) __nv_bfloat16 g_Wq2h[2048u*2048u], g_Wq2l[2048u*2048u];
__device__ __align__(128) __nv_bfloat16 g_Wcqh[2048u*2048u], g_Wcql[2048u*2048u];
__device__ __align__(128) __nv_bfloat16 g_Xh [B_*2048u], g_Xl [B_*2048u];
__device__ __align__(128) __nv_bfloat16 g_Ph [B_*2048u], g_Pl [B_*2048u];
__device__ __align__(128) __nv_bfloat16 g_h1h[B_*2048u], g_h1l[B_*2048u];
__device__ __align__(128) __nv_bfloat16 g_dth[B_*2048u], g_dtl[B_*2048u];
__device__ __align__(128) __nv_bfloat16 g_h2h[B_*2048u], g_h2l[B_*2048u];
__device__ __align__(128) __nv_bfloat16 g_h2qh[B_*2048u], g_h2ql[B_*2048u];
__device__ __align__(128) __nv_bfloat16 g_Xqh[B_*4096u], g_Xql[B_*4096u];
__device__ __align__(128) __nv_bfloat16 g_dqh[B_*2048u], g_dql[B_*2048u];
__device__ __align__(128) float g_gi[B_*6144u];
__device__ __align__(128) float g_gh[B_*6144u];
__device__ __align__(128) float g_bcp[2048], g_ccp[2048], g_bcq[2048], g_ccq[2048];

// ---------------- helpers ----------------
__device__ __forceinline__ float sigmoidf_(float x) { return 1.0f / (1.0f + expf(-x)); }
__device__ __forceinline__ float softplusf_(float x) {
    return fmaxf(x, 0.0f) + log1pf(expf(-fabsf(x)));
}
__device__ __forceinline__ void split2(float v, __nv_bfloat16& h, __nv_bfloat16& l) {
    h = __float2bfloat16(v);
    l = __float2bfloat16(v - __bfloat162float(h));
}
__device__ __forceinline__ uint32_t smem_u32(const void* p) {
    uint32_t a;
    asm("{ .reg .u64 t; cvta.to.shared.u64 t, %1; cvt.u32.u64 %0, t; }" : "=r"(a) : "l"(p));
    return a;
}
__device__ __forceinline__ void cp16(uint32_t s, const void* g) {
    asm volatile("cp.async.cg.shared.global [%0], [%1], 16;" :: "r"(s), "l"(g));
}
__device__ __forceinline__ void cpcommit() { asm volatile("cp.async.commit_group;" ::: "memory"); }
__device__ __forceinline__ void cpwait1() { asm volatile("cp.async.wait_group 1;" ::: "memory"); }
__device__ __forceinline__ void cpwait0() { asm volatile("cp.async.wait_group 0;" ::: "memory"); }
__device__ __forceinline__ void ldm_x4(uint32_t* r, uint32_t addr) {
    asm volatile("ldmatrix.sync.aligned.m8n8.x4.shared.b16 {%0,%1,%2,%3}, [%4];"
                 : "=r"(r[0]), "=r"(r[1]), "=r"(r[2]), "=r"(r[3]) : "r"(addr));
}
__device__ __forceinline__ void mma_bf16(float* c, const uint32_t* a, const uint32_t* b) {
    asm volatile(
        "mma.sync.aligned.m16n8k16.row.col.f32.bf16.bf16.f32 "
        "{%0,%1,%2,%3}, {%4,%5,%6,%7}, {%8,%9}, {%0,%1,%2,%3};"
        : "+f"(c[0]), "+f"(c[1]), "+f"(c[2]), "+f"(c[3])
        : "r"(a[0]), "r"(a[1]), "r"(a[2]), "r"(a[3]), "r"(b[0]), "r"(b[1]));
}
__device__ __forceinline__ uint32_t tadr(uint32_t base, int row, int kc) {
    return base + (uint32_t)(row * 64) + (uint32_t)((kc ^ ((row >> 1) & 3)) << 4);
}

// ---------------- split-bf16 HMMA GEMM: 128x64 tile, 2 CTA/SM ----------------
// warp tile 32(M) x 32(N): wr = wid>>1 (4 rows), wc = wid&1 (2 cols)
// epi: 0 fp32->Cf ; 1 relu->split bf16 (Chi,Clo) ; 2 fused mu/std -> Cf
__global__ void __launch_bounds__(256, 2) gemm_mma(
    const __nv_bfloat16* __restrict__ Ah, const __nv_bfloat16* __restrict__ Al,
    const __nv_bfloat16* __restrict__ Bh, const __nv_bfloat16* __restrict__ Bl,
    const float* __restrict__ bias, const float* __restrict__ csum,
    float* __restrict__ Cf, __nv_bfloat16* __restrict__ Chi, __nv_bfloat16* __restrict__ Clo,
    int K, int ldc, int epi)
{
    extern __shared__ __align__(1024) char smem[];
    const uint32_t sb = smem_u32(smem);
    const int tid = threadIdx.x;
    const int lane = tid & 31, wid = tid >> 5;
    const int wr = wid >> 1, wc = wid & 1;
    const int bm = blockIdx.y * TM;
    const int bn = blockIdx.x * TN;
    const int g = lane >> 3, i8 = lane & 7;

    float acc[2][4][4];
#pragma unroll
    for (int a = 0; a < 2; a++)
#pragma unroll
        for (int b = 0; b < 4; b++)
#pragma unroll
            for (int k = 0; k < 4; k++) acc[a][b][k] = 0.0f;

    auto load_stage = [&](uint32_t sbase, int kpos) {
#pragma unroll
        for (int q = tid; q < 512; q += 256) {
            int row = q >> 2, kc = q & 3;
            uint32_t so = tadr(0, row, kc);
            size_t go = (size_t)(bm + row) * K + kpos + kc * 8;
            cp16(sbase + so, Ah + go);
            cp16(sbase + ATILE + so, Al + go);
        }
        {
            int row = tid >> 2, kc = tid & 3;   // 256 threads = 64 rows x 4 kc
            uint32_t so = tadr(0, row, kc);
            size_t go = (size_t)(bn + row) * K + kpos + kc * 8;
            cp16(sbase + SB_H + so, Bh + go);
            cp16(sbase + SB_L + so, Bl + go);
        }
        cpcommit();
    };

    load_stage(sb, 0);
    load_stage(sb + STG, KC);

    const int nk = K / KC;
    const int aRowBase = wr * 32 + (g & 1) * 8 + i8;
    const int aKsel = g >> 1;
    const int bRowBase = wc * 32 + (g >> 1) * 8 + i8;
    const int bKsel = g & 1;

    int bufc = 0, bufl = 2;
    for (int s = 0; s < nk; s++) {
        if (s < nk - 1) cpwait1(); else cpwait0();
        __syncthreads();
        if (s + 2 < nk) load_stage(sb + (uint32_t)bufl * STG, (s + 2) * KC);

        const uint32_t base = sb + (uint32_t)bufc * STG;
        const uint32_t bAh = base, bAl = base + ATILE;
        const uint32_t bBh = base + SB_H, bBl = base + SB_L;

#pragma unroll
        for (int step = 0; step < 2; step++) {
            const int c0 = step * 2;
            uint32_t Bfh[4][2], Bfl[4][2];
#pragma unroll
            for (int half = 0; half < 2; half++) {
                uint32_t r[4];
                int nrow = bRowBase + half * 16;
                int kc = c0 + bKsel;
                ldm_x4(r, tadr(bBh, nrow, kc));
                Bfh[half * 2 + 0][0] = r[0]; Bfh[half * 2 + 0][1] = r[1];
                Bfh[half * 2 + 1][0] = r[2]; Bfh[half * 2 + 1][1] = r[3];
                ldm_x4(r, tadr(bBl, nrow, kc));
                Bfl[half * 2 + 0][0] = r[0]; Bfl[half * 2 + 0][1] = r[1];
                Bfl[half * 2 + 1][0] = r[2]; Bfl[half * 2 + 1][1] = r[3];
            }
#pragma unroll
            for (int am = 0; am < 2; am++) {
                uint32_t Afh[4], Afl[4];
                int arow = aRowBase + am * 16;
                int kc = c0 + aKsel;
                ldm_x4(Afh, tadr(bAh, arow, kc));
                ldm_x4(Afl, tadr(bAl, arow, kc));
#pragma unroll
                for (int bnf = 0; bnf < 4; bnf++) mma_bf16(acc[am][bnf], Afh, Bfh[bnf]);
#pragma unroll
                for (int bnf = 0; bnf < 4; bnf++) mma_bf16(acc[am][bnf], Afh, Bfl[bnf]);
#pragma unroll
                for (int bnf = 0; bnf < 4; bnf++) mma_bf16(acc[am][bnf], Afl, Bfh[bnf]);
            }
        }
        bufc = (bufc == 2) ? 0 : bufc + 1;
        bufl = (bufl == 2) ? 0 : bufl + 1;
    }

    const int rQ = lane >> 2;
    const int cP = (lane & 3) * 2;
#pragma unroll
    for (int am = 0; am < 2; am++) {
#pragma unroll
        for (int bnf = 0; bnf < 4; bnf++) {
            const int r0 = bm + wr * 32 + am * 16 + rQ;
            const int c  = bn + wc * 32 + bnf * 8 + cP;
            float v0 = acc[am][bnf][0] + bias[c];
            float v1 = acc[am][bnf][1] + bias[c + 1];
            float v2 = acc[am][bnf][2] + bias[c];
            float v3 = acc[am][bnf][3] + bias[c + 1];
            if (epi == 1) {
                v0 = fmaxf(v0, 0.0f); v1 = fmaxf(v1, 0.0f);
                v2 = fmaxf(v2, 0.0f); v3 = fmaxf(v3, 0.0f);
                __nv_bfloat16 h0,l0,h1,l1,h2,l2,h3,l3;
                split2(v0,h0,l0); split2(v1,h1,l1); split2(v2,h2,l2); split2(v3,h3,l3);
                __nv_bfloat162 p01; p01.x = h0; p01.y = h1;
                __nv_bfloat162 q01; q01.x = l0; q01.y = l1;
                __nv_bfloat162 p23; p23.x = h2; p23.y = h3;
                __nv_bfloat162 q23; q23.x = l2; q23.y = l3;
                *reinterpret_cast<__nv_bfloat162*>(Chi + (size_t)r0 * ldc + c) = p01;
                *reinterpret_cast<__nv_bfloat162*>(Clo + (size_t)r0 * ldc + c) = q01;
                *reinterpret_cast<__nv_bfloat162*>(Chi + (size_t)(r0 + 8) * ldc + c) = p23;
                *reinterpret_cast<__nv_bfloat162*>(Clo + (size_t)(r0 + 8) * ldc + c) = q23;
            } else {
                if (epi == 2 && c >= S_) {
                    const float cs0 = csum[c], cs1 = csum[c + 1];
                    v0 = softplusf_(v0 + cs0) + 1e-4f;
                    v1 = softplusf_(v1 + cs1) + 1e-4f;
                    v2 = softplusf_(v2 + cs0) + 1e-4f;
                    v3 = softplusf_(v3 + cs1) + 1e-4f;
                }
                float2 w01; w01.x = v0; w01.y = v1;
                float2 w23; w23.x = v2; w23.y = v3;
                *reinterpret_cast<float2*>(Cf + (size_t)r0 * ldc + c) = w01;
                *reinterpret_cast<float2*>(Cf + (size_t)(r0 + 8) * ldc + c) = w23;
            }
        }
    }
}

// ---------------- transpose + split (vectorized) ----------------
__global__ void transpose_split(const float* __restrict__ W, int K, int N,
                                __nv_bfloat16* __restrict__ Th, __nv_bfloat16* __restrict__ Tl,
                                int ldT, int roff)
{
    __shared__ float t[64][33];
    const int n0 = blockIdx.x * 32, k0 = blockIdx.y * 64;
    const int tx = threadIdx.x, ty = threadIdx.y;
#pragma unroll
    for (int r = 0; r < 64; r += 8)
        t[ty + r][tx] = W[(size_t)(k0 + ty + r) * N + n0 + tx];
    __syncthreads();
#pragma unroll
    for (int r = 0; r < 32; r += 8) {
        const int n = r + ty;
        float v0 = t[2 * tx][n], v1 = t[2 * tx + 1][n];
        __nv_bfloat16 h0, l0, h1, l1;
        split2(v0, h0, l0); split2(v1, h1, l1);
        __nv_bfloat162 H; H.x = h0; H.y = h1;
        __nv_bfloat162 L; L.x = l0; L.y = l1;
        size_t o = (size_t)(roff + n0 + n) * ldT + k0 + 2 * tx;
        *reinterpret_cast<__nv_bfloat162*>(Th + o) = H;
        *reinterpret_cast<__nv_bfloat162*>(Tl + o) = L;
    }
}

// ---------------- bias + 0.54*colsum prep ----------------
__global__ void colprep(const float* __restrict__ bmu, const float* __restrict__ bstd,
                        const __nv_bfloat16* __restrict__ Th, const __nv_bfloat16* __restrict__ Tl,
                        int K, float* __restrict__ bcat, float* __restrict__ ccat)
{
    const int n = blockIdx.x;
    if (n < S_) {
        if (threadIdx.x == 0) { bcat[n] = bmu[n]; ccat[n] = 0.0f; }
        return;
    }
    __shared__ float red[256];
    const __nv_bfloat16* rh = Th + (size_t)n * K;
    const __nv_bfloat16* rl = Tl + (size_t)n * K;
    float s = 0.0f;
    for (int k = threadIdx.x; k < K; k += 256)
        s += __bfloat162float(rh[k]) + __bfloat162float(rl[k]);
    red[threadIdx.x] = s;
    __syncthreads();
    for (int st = 128; st; st >>= 1) {
        if (threadIdx.x < st) red[threadIdx.x] += red[threadIdx.x + st];
        __syncthreads();
    }
    if (threadIdx.x == 0) { bcat[n] = bstd[n - S_]; ccat[n] = 0.54f * red[0]; }
}

// ---------------- fp32 -> split bf16, vectorized x4 ----------------
__global__ void split_convert4(const float* __restrict__ src, int srcW,
                               __nv_bfloat16* __restrict__ dh, __nv_bfloat16* __restrict__ dl,
                               int dstW, int coff)
{
    int idx = blockIdx.x * 256 + threadIdx.x;
    int e = idx * 4;
    int b = e / srcW, j = e - b * srcW;
    float4 v = *reinterpret_cast<const float4*>(src + e);
    __nv_bfloat16 h0,l0,h1,l1,h2,l2,h3,l3;
    split2(v.x,h0,l0); split2(v.y,h1,l1); split2(v.z,h2,l2); split2(v.w,h3,l3);
    __nv_bfloat162 H0; H0.x=h0; H0.y=h1;
    __nv_bfloat162 H1; H1.x=h2; H1.y=h3;
    __nv_bfloat162 L0; L0.x=l0; L0.y=l1;
    __nv_bfloat162 L1; L1.x=l2; L1.y=l3;
    size_t o = (size_t)b * dstW + coff + j;
    *reinterpret_cast<__nv_bfloat162*>(dh + o) = H0;
    *reinterpret_cast<__nv_bfloat162*>(dh + o + 2) = H1;
    *reinterpret_cast<__nv_bfloat162*>(dl + o) = L0;
    *reinterpret_cast<__nv_bfloat162*>(dl + o + 2) = L1;
}

// ---------------- GRU gates, vectorized x2 ----------------
__global__ void gru_gate_k(const float* __restrict__ gi, const float* __restrict__ gh,
                           const float* __restrict__ h,
                           float* __restrict__ outdet,
                           __nv_bfloat16* __restrict__ dh, __nv_bfloat16* __restrict__ dl,
                           __nv_bfloat16* __restrict__ xh, __nv_bfloat16* __restrict__ xl)
{
    const int idx = blockIdx.x * 256 + threadIdx.x;
    const int e = idx * 2;
    const int b = e >> 11;
    const int j = e & (D_ - 1);
    const float* gib = gi + (size_t)b * 3 * D_;
    const float* ghb = gh + (size_t)b * 3 * D_;
    float2 giz = *reinterpret_cast<const float2*>(gib + j);
    float2 gir = *reinterpret_cast<const float2*>(gib + D_ + j);
    float2 gih = *reinterpret_cast<const float2*>(gib + 2 * D_ + j);
    float2 ghz = *reinterpret_cast<const float2*>(ghb + j);
    float2 ghr = *reinterpret_cast<const float2*>(ghb + D_ + j);
    float2 ghh = *reinterpret_cast<const float2*>(ghb + 2 * D_ + j);
    float2 hv  = *reinterpret_cast<const float2*>(h + e);
    float z0 = sigmoidf_(giz.x + ghz.x), z1 = sigmoidf_(giz.y + ghz.y);
    float r0 = sigmoidf_(gir.x + ghr.x), r1 = sigmoidf_(gir.y + ghr.y);
    float n0 = tanhf(gih.x + r0 * ghh.x), n1 = tanhf(gih.y + r1 * ghh.y);
    float v0 = z0 * hv.x + (1.0f - z0) * n0;
    float v1 = z1 * hv.y + (1.0f - z1) * n1;
    if (outdet) {
        float2 o; o.x = v0; o.y = v1;
        *reinterpret_cast<float2*>(outdet + (size_t)b * OUTW + j) = o;
    }
    __nv_bfloat16 h0,l0,h1,l1;
    split2(v0,h0,l0); split2(v1,h1,l1);
    __nv_bfloat162 H; H.x=h0; H.y=h1;
    __nv_bfloat162 L; L.x=l0; L.y=l1;
    *reinterpret_cast<__nv_bfloat162*>(dh + e) = H;
    *reinterpret_cast<__nv_bfloat162*>(dl + e) = L;
    if (xh) {
        *reinterpret_cast<__nv_bfloat162*>(xh + (size_t)b * 4096 + j) = H;
        *reinterpret_cast<__nv_bfloat162*>(xl + (size_t)b * 4096 + j) = L;
    }
}

// ---------------- sample = mu + std * eps, vectorized x2 ----------------
__global__ void sample_k(float* __restrict__ out, int off_mu, int off_std, int off_s,
                         const float* __restrict__ eps)
{
    const int idx = blockIdx.x * 256 + threadIdx.x;
    const int e = idx * 2;
    const int b = e >> 10;
    const int j = e & (S_ - 1);
    float* row = out + (size_t)b * OUTW;
    float2 mu = *reinterpret_cast<const float2*>(row + off_mu + j);
    float2 sd = *reinterpret_cast<const float2*>(row + off_std + j);
    float2 ep = *reinterpret_cast<const float2*>(eps + e);
    float2 o; o.x = mu.x + sd.x * ep.x; o.y = mu.y + sd.y * ep.y;
    *reinterpret_cast<float2*>(row + off_s + j) = o;
}

// ---------------- launch ----------------
extern "C" void kernel_launch(void* const* d_in, const int* in_sizes, int n_in,
                              void* d_out, int out_size)
{
    const float* obs         = (const float*)d_in[0];
    const float* context     = (const float*)d_in[1];
    const float* prev_sample = (const float*)d_in[2];
    const float* prev_h      = (const float*)d_in[3];
    const float* eps_prior   = (const float*)d_in[5];
    const float* eps_post    = (const float*)d_in[6];
    const float* W_p1  = (const float*)d_in[7];
    const float* b_p1  = (const float*)d_in[8];
    const float* Wi    = (const float*)d_in[9];
    const float* Wh    = (const float*)d_in[10];
    const float* bi    = (const float*)d_in[11];
    const float* bh    = (const float*)d_in[12];
    const float* W_p2  = (const float*)d_in[13];
    const float* b_p2  = (const float*)d_in[14];
    const float* W_pmu = (const float*)d_in[15];
    const float* b_pmu = (const float*)d_in[16];
    const float* W_pstd= (const float*)d_in[17];
    const float* b_pstd= (const float*)d_in[18];
    const float* W_q1  = (const float*)d_in[19];
    const float* b_q1  = (const float*)d_in[20];
    const float* W_q2  = (const float*)d_in[21];
    const float* b_q2  = (const float*)d_in[22];
    const float* W_qmu = (const float*)d_in[23];
    const float* b_qmu = (const float*)d_in[24];
    const float* W_qstd= (const float*)d_in[25];
    const float* b_qstd= (const float*)d_in[26];
    float* out = (float*)d_out;

    static cudaStream_t s1 = nullptr, s2 = nullptr;
    static cudaEvent_t evRoot, evWi, evGh, evGru, evC, evP2, evPrior, evXq;
    if (!s1) {
        cudaStreamCreateWithFlags(&s1, cudaStreamNonBlocking);
        cudaStreamCreateWithFlags(&s2, cudaStreamNonBlocking);
        cudaEventCreateWithFlags(&evRoot,  cudaEventDisableTiming);
        cudaEventCreateWithFlags(&evWi,    cudaEventDisableTiming);
        cudaEventCreateWithFlags(&evGh,    cudaEventDisableTiming);
        cudaEventCreateWithFlags(&evGru,   cudaEventDisableTiming);
        cudaEventCreateWithFlags(&evC,     cudaEventDisableTiming);
        cudaEventCreateWithFlags(&evP2,    cudaEventDisableTiming);
        cudaEventCreateWithFlags(&evPrior, cudaEventDisableTiming);
        cudaEventCreateWithFlags(&evXq,    cudaEventDisableTiming);
    }
    cudaFuncSetAttribute(gemm_mma, cudaFuncAttributeMaxDynamicSharedMemorySize, SMEMB);

#define SYM(p, s) float* p; cudaGetSymbolAddress((void**)&p, s)
#define SYMB(p, s) __nv_bfloat16* p; cudaGetSymbolAddress((void**)&p, s)
    SYMB(Wp1h,g_Wp1h); SYMB(Wp1l,g_Wp1l); SYMB(Wih,g_Wih); SYMB(Wil,g_Wil);
    SYMB(Whh,g_Whh); SYMB(Whl,g_Whl); SYMB(Wp2h,g_Wp2h); SYMB(Wp2l,g_Wp2l);
    SYMB(Wcph,g_Wcph); SYMB(Wcpl,g_Wcpl); SYMB(Wq1h,g_Wq1h); SYMB(Wq1l,g_Wq1l);
    SYMB(Wq2h,g_Wq2h); SYMB(Wq2l,g_Wq2l); SYMB(Wcqh,g_Wcqh); SYMB(Wcql,g_Wcql);
    SYMB(Xh,g_Xh); SYMB(Xl,g_Xl); SYMB(Ph,g_Ph); SYMB(Pl,g_Pl);
    SYMB(h1h,g_h1h); SYMB(h1l,g_h1l); SYMB(dth,g_dth); SYMB(dtl,g_dtl);
    SYMB(h2h,g_h2h); SYMB(h2l,g_h2l); SYMB(h2qh,g_h2qh); SYMB(h2ql,g_h2ql);
    SYMB(Xqh,g_Xqh); SYMB(Xql,g_Xql); SYMB(dqh,g_dqh); SYMB(dql,g_dql);
    SYM(giF,g_gi); SYM(ghF,g_gh);
    SYM(bcp,g_bcp); SYM(ccp,g_ccp); SYM(bcq,g_bcq); SYM(ccq,g_ccq);
#undef SYM
#undef SYMB

    const dim3 tb(32, 8);

    cudaEventRecord(evRoot, 0);
    cudaStreamWaitEvent(s1, evRoot, 0);
    cudaStreamWaitEvent(s2, evRoot, 0);

    // ---- s0: p1 prep + p1 GEMM (GEMM = 4th launch, keeps ncu on the GEMM) ----
    split_convert4<<<1024, 256, 0, 0>>>(prev_sample, 1024, Xh, Xl, 2048, 0);
    split_convert4<<<1024, 256, 0, 0>>>(context,     1024, Xh, Xl, 2048, 1024);
    transpose_split<<<dim3(64, 32), tb, 0, 0>>>(W_p1, 2048, 2048, Wp1h, Wp1l, 2048, 0);
    gemm_mma<<<dim3(2048/TN, 8), 256, SMEMB, 0>>>(Xh, Xl, Wp1h, Wp1l, b_p1, nullptr,
        nullptr, h1h, h1l, 2048, 2048, 1);

    // ---- s1: GRU-h prep + gh GEMM ----
    split_convert4<<<2048, 256, 0, s1>>>(prev_h, 2048, Ph, Pl, 2048, 0);
    transpose_split<<<dim3(192, 32), tb, 0, s1>>>(Wh, 2048, 6144, Whh, Whl, 2048, 0);
    gemm_mma<<<dim3(6144/TN, 8), 256, SMEMB, s1>>>(Ph, Pl, Whh, Whl, bh, nullptr,
        ghF, nullptr, nullptr, 2048, 6144, 0);
    cudaEventRecord(evGh, s1);

    // ---- s2: remaining prep ----
    transpose_split<<<dim3(192, 32), tb, 0, s2>>>(Wi, 2048, 6144, Wih, Wil, 2048, 0);
    cudaEventRecord(evWi, s2);
    split_convert4<<<2048, 256, 0, s2>>>(obs, 2048, Xqh, Xql, 4096, 2048);
    cudaEventRecord(evXq, s2);
    transpose_split<<<dim3(64, 64), tb, 0, s2>>>(W_q1, 4096, 2048, Wq1h, Wq1l, 4096, 0);
    transpose_split<<<dim3(64, 32), tb, 0, s2>>>(W_q2, 2048, 2048, Wq2h, Wq2l, 2048, 0);
    transpose_split<<<dim3(32, 32), tb, 0, s2>>>(W_qmu, 2048, 1024, Wcqh, Wcql, 2048, 0);
    transpose_split<<<dim3(32, 32), tb, 0, s2>>>(W_qstd,2048, 1024, Wcqh, Wcql, 2048, 1024);
    colprep<<<2048, 256, 0, s2>>>(b_qmu, b_qstd, Wcqh, Wcql, 2048, bcq, ccq);
    cudaEventRecord(evC, s2);
    transpose_split<<<dim3(64, 32), tb, 0, s2>>>(W_p2, 2048, 2048, Wp2h, Wp2l, 2048, 0);
    transpose_split<<<dim3(32, 32), tb, 0, s2>>>(W_pmu, 2048, 1024, Wcph, Wcpl, 2048, 0);
    transpose_split<<<dim3(32, 32), tb, 0, s2>>>(W_pstd,2048, 1024, Wcph, Wcpl, 2048, 1024);
    colprep<<<2048, 256, 0, s2>>>(b_pmu, b_pstd, Wcph, Wcpl, 2048, bcp, ccp);
    cudaEventRecord(evP2, s2);

    // ---- s0: prior chain ----
    cudaStreamWaitEvent(0, evWi, 0);
    gemm_mma<<<dim3(6144/TN, 8), 256, SMEMB, 0>>>(h1h, h1l, Wih, Wil, bi, nullptr,
        giF, nullptr, nullptr, 2048, 6144, 0);
    cudaStreamWaitEvent(0, evGh, 0);
    cudaStreamWaitEvent(0, evXq, 0);
    gru_gate_k<<<(B_ * D_) / 512, 256, 0, 0>>>(giF, ghF, prev_h, out + 3 * S_, dth, dtl, Xqh, Xql);
    cudaEventRecord(evGru, 0);

    // ---- s1: prior tail ----
    cudaStreamWaitEvent(s1, evGru, 0);
    cudaStreamWaitEvent(s1, evP2, 0);
    gemm_mma<<<dim3(2048/TN, 8), 256, SMEMB, s1>>>(dth, dtl, Wp2h, Wp2l, b_p2, nullptr,
        nullptr, h2h, h2l, 2048, 2048, 1);
    gemm_mma<<<dim3(2048/TN, 8), 256, SMEMB, s1>>>(h2h, h2l, Wcph, Wcpl, bcp, ccp,
        out, nullptr, nullptr, 2048, OUTW, 2);
    sample_k<<<(B_ * S_) / 512, 256, 0, s1>>>(out, 0, S_, 2 * S_, eps_prior);
    cudaEventRecord(evPrior, s1);

    // ---- s0: posterior chain ----
    cudaStreamWaitEvent(0, evC, 0);
    gemm_mma<<<dim3(2048/TN, 8), 256, SMEMB, 0>>>(Xqh, Xql, Wq1h, Wq1l, b_q1, nullptr,
        nullptr, h1h, h1l, 4096, 2048, 1);
    gemm_mma<<<dim3(6144/TN, 8), 256, SMEMB, 0>>>(h1h, h1l, Wih, Wil, bi, nullptr,
        giF, nullptr, nullptr, 2048, 6144, 0);
    gru_gate_k<<<(B_ * D_) / 512, 256, 0, 0>>>(giF, ghF, prev_h, nullptr, dqh, dql, nullptr, nullptr);
    gemm_mma<<<dim3(2048/TN, 8), 256, SMEMB, 0>>>(dqh, dql, Wq2h, Wq2l, b_q2, nullptr,
        nullptr, h2qh, h2ql, 2048, 2048, 1);
    gemm_mma<<<dim3(2048/TN, 8), 256, SMEMB, 0>>>(h2qh, h2ql, Wcqh, Wcql, bcq, ccq,
        out + 5 * S_, nullptr, nullptr, 2048, OUTW, 2);
    sample_k<<<(B_ * S_) / 512, 256, 0, 0>>>(out, 5 * S_, 6 * S_, 7 * S_, eps_post);

    cudaStreamWaitEvent(0, evPrior, 0);

    (void)in_sizes; (void)n_in; (void)out_size;
}

// round 10
// speedup vs baseline: 3.2127x; 1.1728x over previous
#include <cuda_runtime.h>
#include <cuda_bf16.h>
#include <math.h>
#include <stdint.h>

#define B_   1024
#define S_   1024
#define D_   2048
#define E_   2048
#define OUTW 8192

#define TM 64
#define TN 64
#define KC 32
#define NSTAGE 3
// stage: A_hi 4KB + A_lo 4KB + B_hi 4KB + B_lo 4KB = 16KB
#define ATILE 4096u
#define BTILE 4096u
#define SB_H  (2u * ATILE)
#define SB_L  (2u * ATILE + BTILE)
#define STG   (2u * ATILE + 2u * BTILE)
#define SMEMB ((int)(NSTAGE * STG))

// ---------------- device scratch ----------------
__device__ __align__(128) __nv_bfloat16 g_Wp1h[2048u*2048u], g_Wp1l[2048u*2048u];
__device__ __align__(128) __nv_bfloat16 g_Wih [6144u*2048u], g_Wil [6144u*2048u];
__device__ __align__(128) __nv_bfloat16 g_Whh [6144u*2048u], g_Whl [6144u*2048u];
__device__ __align__(128) __nv_bfloat16 g_Wp2h[2048u*2048u], g_Wp2l[2048u*2048u];
__device__ __align__(128) __nv_bfloat16 g_Wcph[2048u*2048u], g_Wcpl[2048u*2048u];
__device__ __align__(128) __nv_bfloat16 g_Wq1h[2048u*4096u], g_Wq1l[2048u*4096u];
__device__ __align__(128) __nv_bfloat16 g_Wq2h[2048u*2048u], g_Wq2l[2048u*2048u];
__device__ __align__(128) __nv_bfloat16 g_Wcqh[2048u*2048u], g_Wcql[2048u*2048u];
__device__ __align__(128) __nv_bfloat16 g_Xh [B_*2048u], g_Xl [B_*2048u];
__device__ __align__(128) __nv_bfloat16 g_Ph [B_*2048u], g_Pl [B_*2048u];
__device__ __align__(128) __nv_bfloat16 g_h1h[B_*2048u], g_h1l[B_*2048u];
__device__ __align__(128) __nv_bfloat16 g_dth[B_*2048u], g_dtl[B_*2048u];
__device__ __align__(128) __nv_bfloat16 g_h2h[B_*2048u], g_h2l[B_*2048u];
__device__ __align__(128) __nv_bfloat16 g_h2qh[B_*2048u], g_h2ql[B_*2048u];
__device__ __align__(128) __nv_bfloat16 g_Xqh[B_*4096u], g_Xql[B_*4096u];
__device__ __align__(128) __nv_bfloat16 g_dqh[B_*2048u], g_dql[B_*2048u];
__device__ __align__(128) float g_gi[B_*6144u];
__device__ __align__(128) float g_gh[B_*6144u];
__device__ __align__(128) float g_bcp[2048], g_ccp[2048], g_bcq[2048], g_ccq[2048];

// ---------------- helpers ----------------
__device__ __forceinline__ float sigmoidf_(float x) { return 1.0f / (1.0f + expf(-x)); }
__device__ __forceinline__ float softplusf_(float x) {
    return fmaxf(x, 0.0f) + log1pf(expf(-fabsf(x)));
}
__device__ __forceinline__ void split2(float v, __nv_bfloat16& h, __nv_bfloat16& l) {
    h = __float2bfloat16(v);
    l = __float2bfloat16(v - __bfloat162float(h));
}
__device__ __forceinline__ uint32_t smem_u32(const void* p) {
    uint32_t a;
    asm("{ .reg .u64 t; cvta.to.shared.u64 t, %1; cvt.u32.u64 %0, t; }" : "=r"(a) : "l"(p));
    return a;
}
__device__ __forceinline__ void cp16(uint32_t s, const void* g) {
    asm volatile("cp.async.cg.shared.global [%0], [%1], 16;" :: "r"(s), "l"(g));
}
__device__ __forceinline__ void cpcommit() { asm volatile("cp.async.commit_group;" ::: "memory"); }
__device__ __forceinline__ void cpwait1() { asm volatile("cp.async.wait_group 1;" ::: "memory"); }
__device__ __forceinline__ void cpwait0() { asm volatile("cp.async.wait_group 0;" ::: "memory"); }
__device__ __forceinline__ void ldm_x4(uint32_t* r, uint32_t addr) {
    asm volatile("ldmatrix.sync.aligned.m8n8.x4.shared.b16 {%0,%1,%2,%3}, [%4];"
                 : "=r"(r[0]), "=r"(r[1]), "=r"(r[2]), "=r"(r[3]) : "r"(addr));
}
__device__ __forceinline__ void mma_bf16(float* c, const uint32_t* a, const uint32_t* b) {
    asm volatile(
        "mma.sync.aligned.m16n8k16.row.col.f32.bf16.bf16.f32 "
        "{%0,%1,%2,%3}, {%4,%5,%6,%7}, {%8,%9}, {%0,%1,%2,%3};"
        : "+f"(c[0]), "+f"(c[1]), "+f"(c[2]), "+f"(c[3])
        : "r"(a[0]), "r"(a[1]), "r"(a[2]), "r"(a[3]), "r"(b[0]), "r"(b[1]));
}
__device__ __forceinline__ uint32_t tadr(uint32_t base, int row, int kc) {
    return base + (uint32_t)(row * 64) + (uint32_t)((kc ^ ((row >> 1) & 3)) << 4);
}

// ---------------- split-bf16 HMMA GEMM: 64x64 tile, 128 thr, 4 CTA/SM ----------------
// warp tile 32(M) x 32(N): wr = wid>>1, wc = wid&1
// epi: 0 fp32->Cf ; 1 relu->split bf16 (Chi,Clo) ; 2 fused mu/std -> Cf
__global__ void __launch_bounds__(128, 4) gemm_mma(
    const __nv_bfloat16* __restrict__ Ah, const __nv_bfloat16* __restrict__ Al,
    const __nv_bfloat16* __restrict__ Bh, const __nv_bfloat16* __restrict__ Bl,
    const float* __restrict__ bias, const float* __restrict__ csum,
    float* __restrict__ Cf, __nv_bfloat16* __restrict__ Chi, __nv_bfloat16* __restrict__ Clo,
    int K, int ldc, int epi)
{
    extern __shared__ __align__(1024) char smem[];
    const uint32_t sb = smem_u32(smem);
    const int tid = threadIdx.x;
    const int lane = tid & 31, wid = tid >> 5;
    const int wr = wid >> 1, wc = wid & 1;
    const int bm = blockIdx.y * TM;
    const int bn = blockIdx.x * TN;
    const int g = lane >> 3, i8 = lane & 7;

    float acc[2][4][4];
#pragma unroll
    for (int a = 0; a < 2; a++)
#pragma unroll
        for (int b = 0; b < 4; b++)
#pragma unroll
            for (int k = 0; k < 4; k++) acc[a][b][k] = 0.0f;

    auto load_stage = [&](uint32_t sbase, int kpos) {
#pragma unroll
        for (int q = tid; q < 256; q += 128) {
            int row = q >> 2, kc = q & 3;
            uint32_t so = tadr(0, row, kc);
            size_t goA = (size_t)(bm + row) * K + kpos + kc * 8;
            size_t goB = (size_t)(bn + row) * K + kpos + kc * 8;
            cp16(sbase + so, Ah + goA);
            cp16(sbase + ATILE + so, Al + goA);
            cp16(sbase + SB_H + so, Bh + goB);
            cp16(sbase + SB_L + so, Bl + goB);
        }
        cpcommit();
    };

    load_stage(sb, 0);
    load_stage(sb + STG, KC);

    const int nk = K / KC;
    const int aRowBase = wr * 32 + (g & 1) * 8 + i8;
    const int aKsel = g >> 1;
    const int bRowBase = wc * 32 + (g >> 1) * 8 + i8;
    const int bKsel = g & 1;

    int bufc = 0, bufl = 2;
    for (int s = 0; s < nk; s++) {
        if (s < nk - 1) cpwait1(); else cpwait0();
        __syncthreads();
        if (s + 2 < nk) load_stage(sb + (uint32_t)bufl * STG, (s + 2) * KC);

        const uint32_t base = sb + (uint32_t)bufc * STG;
        const uint32_t bAh = base, bAl = base + ATILE;
        const uint32_t bBh = base + SB_H, bBl = base + SB_L;

#pragma unroll
        for (int step = 0; step < 2; step++) {
            const int c0 = step * 2;
            uint32_t Bfh[4][2], Bfl[4][2];
#pragma unroll
            for (int half = 0; half < 2; half++) {
                uint32_t r[4];
                int nrow = bRowBase + half * 16;
                int kc = c0 + bKsel;
                ldm_x4(r, tadr(bBh, nrow, kc));
                Bfh[half * 2 + 0][0] = r[0]; Bfh[half * 2 + 0][1] = r[1];
                Bfh[half * 2 + 1][0] = r[2]; Bfh[half * 2 + 1][1] = r[3];
                ldm_x4(r, tadr(bBl, nrow, kc));
                Bfl[half * 2 + 0][0] = r[0]; Bfl[half * 2 + 0][1] = r[1];
                Bfl[half * 2 + 1][0] = r[2]; Bfl[half * 2 + 1][1] = r[3];
            }
#pragma unroll
            for (int am = 0; am < 2; am++) {
                uint32_t Afh[4], Afl[4];
                int arow = aRowBase + am * 16;
                int kc = c0 + aKsel;
                ldm_x4(Afh, tadr(bAh, arow, kc));
                ldm_x4(Afl, tadr(bAl, arow, kc));
#pragma unroll
                for (int bnf = 0; bnf < 4; bnf++) mma_bf16(acc[am][bnf], Afh, Bfh[bnf]);
#pragma unroll
                for (int bnf = 0; bnf < 4; bnf++) mma_bf16(acc[am][bnf], Afh, Bfl[bnf]);
#pragma unroll
                for (int bnf = 0; bnf < 4; bnf++) mma_bf16(acc[am][bnf], Afl, Bfh[bnf]);
            }
        }
        bufc = (bufc == 2) ? 0 : bufc + 1;
        bufl = (bufl == 2) ? 0 : bufl + 1;
    }

    const int rQ = lane >> 2;
    const int cP = (lane & 3) * 2;
#pragma unroll
    for (int am = 0; am < 2; am++) {
#pragma unroll
        for (int bnf = 0; bnf < 4; bnf++) {
            const int r0 = bm + wr * 32 + am * 16 + rQ;
            const int c  = bn + wc * 32 + bnf * 8 + cP;
            float v0 = acc[am][bnf][0] + bias[c];
            float v1 = acc[am][bnf][1] + bias[c + 1];
            float v2 = acc[am][bnf][2] + bias[c];
            float v3 = acc[am][bnf][3] + bias[c + 1];
            if (epi == 1) {
                v0 = fmaxf(v0, 0.0f); v1 = fmaxf(v1, 0.0f);
                v2 = fmaxf(v2, 0.0f); v3 = fmaxf(v3, 0.0f);
                __nv_bfloat16 h0,l0,h1,l1,h2,l2,h3,l3;
                split2(v0,h0,l0); split2(v1,h1,l1); split2(v2,h2,l2); split2(v3,h3,l3);
                __nv_bfloat162 p01; p01.x = h0; p01.y = h1;
                __nv_bfloat162 q01; q01.x = l0; q01.y = l1;
                __nv_bfloat162 p23; p23.x = h2; p23.y = h3;
                __nv_bfloat162 q23; q23.x = l2; q23.y = l3;
                *reinterpret_cast<__nv_bfloat162*>(Chi + (size_t)r0 * ldc + c) = p01;
                *reinterpret_cast<__nv_bfloat162*>(Clo + (size_t)r0 * ldc + c) = q01;
                *reinterpret_cast<__nv_bfloat162*>(Chi + (size_t)(r0 + 8) * ldc + c) = p23;
                *reinterpret_cast<__nv_bfloat162*>(Clo + (size_t)(r0 + 8) * ldc + c) = q23;
            } else {
                if (epi == 2 && c >= S_) {
                    const float cs0 = csum[c], cs1 = csum[c + 1];
                    v0 = softplusf_(v0 + cs0) + 1e-4f;
                    v1 = softplusf_(v1 + cs1) + 1e-4f;
                    v2 = softplusf_(v2 + cs0) + 1e-4f;
                    v3 = softplusf_(v3 + cs1) + 1e-4f;
                }
                float2 w01; w01.x = v0; w01.y = v1;
                float2 w23; w23.x = v2; w23.y = v3;
                *reinterpret_cast<float2*>(Cf + (size_t)r0 * ldc + c) = w01;
                *reinterpret_cast<float2*>(Cf + (size_t)(r0 + 8) * ldc + c) = w23;
            }
        }
    }
}

// ---------------- transpose + split (vectorized) ----------------
__global__ void transpose_split(const float* __restrict__ W, int K, int N,
                                __nv_bfloat16* __restrict__ Th, __nv_bfloat16* __restrict__ Tl,
                                int ldT, int roff)
{
    __shared__ float t[64][33];
    const int n0 = blockIdx.x * 32, k0 = blockIdx.y * 64;
    const int tx = threadIdx.x, ty = threadIdx.y;
#pragma unroll
    for (int r = 0; r < 64; r += 8)
        t[ty + r][tx] = W[(size_t)(k0 + ty + r) * N + n0 + tx];
    __syncthreads();
#pragma unroll
    for (int r = 0; r < 32; r += 8) {
        const int n = r + ty;
        float v0 = t[2 * tx][n], v1 = t[2 * tx + 1][n];
        __nv_bfloat16 h0, l0, h1, l1;
        split2(v0, h0, l0); split2(v1, h1, l1);
        __nv_bfloat162 H; H.x = h0; H.y = h1;
        __nv_bfloat162 L; L.x = l0; L.y = l1;
        size_t o = (size_t)(roff + n0 + n) * ldT + k0 + 2 * tx;
        *reinterpret_cast<__nv_bfloat162*>(Th + o) = H;
        *reinterpret_cast<__nv_bfloat162*>(Tl + o) = L;
    }
}

// ---------------- bias + 0.54*colsum prep ----------------
__global__ void colprep(const float* __restrict__ bmu, const float* __restrict__ bstd,
                        const __nv_bfloat16* __restrict__ Th, const __nv_bfloat16* __restrict__ Tl,
                        int K, float* __restrict__ bcat, float* __restrict__ ccat)
{
    const int n = blockIdx.x;
    if (n < S_) {
        if (threadIdx.x == 0) { bcat[n] = bmu[n]; ccat[n] = 0.0f; }
        return;
    }
    __shared__ float red[256];
    const __nv_bfloat16* rh = Th + (size_t)n * K;
    const __nv_bfloat16* rl = Tl + (size_t)n * K;
    float s = 0.0f;
    for (int k = threadIdx.x; k < K; k += 256)
        s += __bfloat162float(rh[k]) + __bfloat162float(rl[k]);
    red[threadIdx.x] = s;
    __syncthreads();
    for (int st = 128; st; st >>= 1) {
        if (threadIdx.x < st) red[threadIdx.x] += red[threadIdx.x + st];
        __syncthreads();
    }
    if (threadIdx.x == 0) { bcat[n] = bstd[n - S_]; ccat[n] = 0.54f * red[0]; }
}

// ---------------- fp32 -> split bf16, vectorized x4 ----------------
__global__ void split_convert4(const float* __restrict__ src, int srcW,
                               __nv_bfloat16* __restrict__ dh, __nv_bfloat16* __restrict__ dl,
                               int dstW, int coff)
{
    int idx = blockIdx.x * 256 + threadIdx.x;
    int e = idx * 4;
    int b = e / srcW, j = e - b * srcW;
    float4 v = *reinterpret_cast<const float4*>(src + e);
    __nv_bfloat16 h0,l0,h1,l1,h2,l2,h3,l3;
    split2(v.x,h0,l0); split2(v.y,h1,l1); split2(v.z,h2,l2); split2(v.w,h3,l3);
    __nv_bfloat162 H0; H0.x=h0; H0.y=h1;
    __nv_bfloat162 H1; H1.x=h2; H1.y=h3;
    __nv_bfloat162 L0; L0.x=l0; L0.y=l1;
    __nv_bfloat162 L1; L1.x=l2; L1.y=l3;
    size_t o = (size_t)b * dstW + coff + j;
    *reinterpret_cast<__nv_bfloat162*>(dh + o) = H0;
    *reinterpret_cast<__nv_bfloat162*>(dh + o + 2) = H1;
    *reinterpret_cast<__nv_bfloat162*>(dl + o) = L0;
    *reinterpret_cast<__nv_bfloat162*>(dl + o + 2) = L1;
}

// ---------------- GRU gates, vectorized x2 ----------------
__global__ void gru_gate_k(const float* __restrict__ gi, const float* __restrict__ gh,
                           const float* __restrict__ h,
                           float* __restrict__ outdet,
                           __nv_bfloat16* __restrict__ dh, __nv_bfloat16* __restrict__ dl,
                           __nv_bfloat16* __restrict__ xh, __nv_bfloat16* __restrict__ xl)
{
    const int idx = blockIdx.x * 256 + threadIdx.x;
    const int e = idx * 2;
    const int b = e >> 11;
    const int j = e & (D_ - 1);
    const float* gib = gi + (size_t)b * 3 * D_;
    const float* ghb = gh + (size_t)b * 3 * D_;
    float2 giz = *reinterpret_cast<const float2*>(gib + j);
    float2 gir = *reinterpret_cast<const float2*>(gib + D_ + j);
    float2 gih = *reinterpret_cast<const float2*>(gib + 2 * D_ + j);
    float2 ghz = *reinterpret_cast<const float2*>(ghb + j);
    float2 ghr = *reinterpret_cast<const float2*>(ghb + D_ + j);
    float2 ghh = *reinterpret_cast<const float2*>(ghb + 2 * D_ + j);
    float2 hv  = *reinterpret_cast<const float2*>(h + e);
    float z0 = sigmoidf_(giz.x + ghz.x), z1 = sigmoidf_(giz.y + ghz.y);
    float r0 = sigmoidf_(gir.x + ghr.x), r1 = sigmoidf_(gir.y + ghr.y);
    float n0 = tanhf(gih.x + r0 * ghh.x), n1 = tanhf(gih.y + r1 * ghh.y);
    float v0 = z0 * hv.x + (1.0f - z0) * n0;
    float v1 = z1 * hv.y + (1.0f - z1) * n1;
    if (outdet) {
        float2 o; o.x = v0; o.y = v1;
        *reinterpret_cast<float2*>(outdet + (size_t)b * OUTW + j) = o;
    }
    __nv_bfloat16 h0,l0,h1,l1;
    split2(v0,h0,l0); split2(v1,h1,l1);
    __nv_bfloat162 H; H.x=h0; H.y=h1;
    __nv_bfloat162 L; L.x=l0; L.y=l1;
    *reinterpret_cast<__nv_bfloat162*>(dh + e) = H;
    *reinterpret_cast<__nv_bfloat162*>(dl + e) = L;
    if (xh) {
        *reinterpret_cast<__nv_bfloat162*>(xh + (size_t)b * 4096 + j) = H;
        *reinterpret_cast<__nv_bfloat162*>(xl + (size_t)b * 4096 + j) = L;
    }
}

// ---------------- sample = mu + std * eps, vectorized x2 ----------------
__global__ void sample_k(float* __restrict__ out, int off_mu, int off_std, int off_s,
                         const float* __restrict__ eps)
{
    const int idx = blockIdx.x * 256 + threadIdx.x;
    const int e = idx * 2;
    const int b = e >> 10;
    const int j = e & (S_ - 1);
    float* row = out + (size_t)b * OUTW;
    float2 mu = *reinterpret_cast<const float2*>(row + off_mu + j);
    float2 sd = *reinterpret_cast<const float2*>(row + off_std + j);
    float2 ep = *reinterpret_cast<const float2*>(eps + e);
    float2 o; o.x = mu.x + sd.x * ep.x; o.y = mu.y + sd.y * ep.y;
    *reinterpret_cast<float2*>(row + off_s + j) = o;
}

// ---------------- launch ----------------
extern "C" void kernel_launch(void* const* d_in, const int* in_sizes, int n_in,
                              void* d_out, int out_size)
{
    const float* obs         = (const float*)d_in[0];
    const float* context     = (const float*)d_in[1];
    const float* prev_sample = (const float*)d_in[2];
    const float* prev_h      = (const float*)d_in[3];
    const float* eps_prior   = (const float*)d_in[5];
    const float* eps_post    = (const float*)d_in[6];
    const float* W_p1  = (const float*)d_in[7];
    const float* b_p1  = (const float*)d_in[8];
    const float* Wi    = (const float*)d_in[9];
    const float* Wh    = (const float*)d_in[10];
    const float* bi    = (const float*)d_in[11];
    const float* bh    = (const float*)d_in[12];
    const float* W_p2  = (const float*)d_in[13];
    const float* b_p2  = (const float*)d_in[14];
    const float* W_pmu = (const float*)d_in[15];
    const float* b_pmu = (const float*)d_in[16];
    const float* W_pstd= (const float*)d_in[17];
    const float* b_pstd= (const float*)d_in[18];
    const float* W_q1  = (const float*)d_in[19];
    const float* b_q1  = (const float*)d_in[20];
    const float* W_q2  = (const float*)d_in[21];
    const float* b_q2  = (const float*)d_in[22];
    const float* W_qmu = (const float*)d_in[23];
    const float* b_qmu = (const float*)d_in[24];
    const float* W_qstd= (const float*)d_in[25];
    const float* b_qstd= (const float*)d_in[26];
    float* out = (float*)d_out;

    static cudaStream_t s1 = nullptr, s2 = nullptr;
    static cudaEvent_t evRoot, evWi, evGh, evGru, evC, evP2, evPrior, evXq;
    if (!s1) {
        cudaStreamCreateWithFlags(&s1, cudaStreamNonBlocking);
        cudaStreamCreateWithFlags(&s2, cudaStreamNonBlocking);
        cudaEventCreateWithFlags(&evRoot,  cudaEventDisableTiming);
        cudaEventCreateWithFlags(&evWi,    cudaEventDisableTiming);
        cudaEventCreateWithFlags(&evGh,    cudaEventDisableTiming);
        cudaEventCreateWithFlags(&evGru,   cudaEventDisableTiming);
        cudaEventCreateWithFlags(&evC,     cudaEventDisableTiming);
        cudaEventCreateWithFlags(&evP2,    cudaEventDisableTiming);
        cudaEventCreateWithFlags(&evPrior, cudaEventDisableTiming);
        cudaEventCreateWithFlags(&evXq,    cudaEventDisableTiming);
    }
    cudaFuncSetAttribute(gemm_mma, cudaFuncAttributeMaxDynamicSharedMemorySize, SMEMB);

#define SYM(p, s) float* p; cudaGetSymbolAddress((void**)&p, s)
#define SYMB(p, s) __nv_bfloat16* p; cudaGetSymbolAddress((void**)&p, s)
    SYMB(Wp1h,g_Wp1h); SYMB(Wp1l,g_Wp1l); SYMB(Wih,g_Wih); SYMB(Wil,g_Wil);
    SYMB(Whh,g_Whh); SYMB(Whl,g_Whl); SYMB(Wp2h,g_Wp2h); SYMB(Wp2l,g_Wp2l);
    SYMB(Wcph,g_Wcph); SYMB(Wcpl,g_Wcpl); SYMB(Wq1h,g_Wq1h); SYMB(Wq1l,g_Wq1l);
    SYMB(Wq2h,g_Wq2h); SYMB(Wq2l,g_Wq2l); SYMB(Wcqh,g_Wcqh); SYMB(Wcql,g_Wcql);
    SYMB(Xh,g_Xh); SYMB(Xl,g_Xl); SYMB(Ph,g_Ph); SYMB(Pl,g_Pl);
    SYMB(h1h,g_h1h); SYMB(h1l,g_h1l); SYMB(dth,g_dth); SYMB(dtl,g_dtl);
    SYMB(h2h,g_h2h); SYMB(h2l,g_h2l); SYMB(h2qh,g_h2qh); SYMB(h2ql,g_h2ql);
    SYMB(Xqh,g_Xqh); SYMB(Xql,g_Xql); SYMB(dqh,g_dqh); SYMB(dql,g_dql);
    SYM(giF,g_gi); SYM(ghF,g_gh);
    SYM(bcp,g_bcp); SYM(ccp,g_ccp); SYM(bcq,g_bcq); SYM(ccq,g_ccq);
#undef SYM
#undef SYMB

    const dim3 tb(32, 8);
    const dim3 gN2(2048 / TN, B_ / TM);   // (32, 16)
    const dim3 gN6(6144 / TN, B_ / TM);   // (96, 16)

    cudaEventRecord(evRoot, 0);
    cudaStreamWaitEvent(s1, evRoot, 0);
    cudaStreamWaitEvent(s2, evRoot, 0);

    // ---- s0: p1 prep + p1 GEMM (GEMM = 4th launch, keeps ncu on the GEMM) ----
    split_convert4<<<1024, 256, 0, 0>>>(prev_sample, 1024, Xh, Xl, 2048, 0);
    split_convert4<<<1024, 256, 0, 0>>>(context,     1024, Xh, Xl, 2048, 1024);
    transpose_split<<<dim3(64, 32), tb, 0, 0>>>(W_p1, 2048, 2048, Wp1h, Wp1l, 2048, 0);
    gemm_mma<<<gN2, 128, SMEMB, 0>>>(Xh, Xl, Wp1h, Wp1l, b_p1, nullptr,
        nullptr, h1h, h1l, 2048, 2048, 1);

    // ---- s1: GRU-h prep + gh GEMM ----
    split_convert4<<<2048, 256, 0, s1>>>(prev_h, 2048, Ph, Pl, 2048, 0);
    transpose_split<<<dim3(192, 32), tb, 0, s1>>>(Wh, 2048, 6144, Whh, Whl, 2048, 0);
    gemm_mma<<<gN6, 128, SMEMB, s1>>>(Ph, Pl, Whh, Whl, bh, nullptr,
        ghF, nullptr, nullptr, 2048, 6144, 0);
    cudaEventRecord(evGh, s1);

    // ---- s2: remaining prep ----
    transpose_split<<<dim3(192, 32), tb, 0, s2>>>(Wi, 2048, 6144, Wih, Wil, 2048, 0);
    cudaEventRecord(evWi, s2);
    split_convert4<<<2048, 256, 0, s2>>>(obs, 2048, Xqh, Xql, 4096, 2048);
    cudaEventRecord(evXq, s2);
    transpose_split<<<dim3(64, 64), tb, 0, s2>>>(W_q1, 4096, 2048, Wq1h, Wq1l, 4096, 0);
    transpose_split<<<dim3(64, 32), tb, 0, s2>>>(W_q2, 2048, 2048, Wq2h, Wq2l, 2048, 0);
    transpose_split<<<dim3(32, 32), tb, 0, s2>>>(W_qmu, 2048, 1024, Wcqh, Wcql, 2048, 0);
    transpose_split<<<dim3(32, 32), tb, 0, s2>>>(W_qstd,2048, 1024, Wcqh, Wcql, 2048, 1024);
    colprep<<<2048, 256, 0, s2>>>(b_qmu, b_qstd, Wcqh, Wcql, 2048, bcq, ccq);
    cudaEventRecord(evC, s2);
    transpose_split<<<dim3(64, 32), tb, 0, s2>>>(W_p2, 2048, 2048, Wp2h, Wp2l, 2048, 0);
    transpose_split<<<dim3(32, 32), tb, 0, s2>>>(W_pmu, 2048, 1024, Wcph, Wcpl, 2048, 0);
    transpose_split<<<dim3(32, 32), tb, 0, s2>>>(W_pstd,2048, 1024, Wcph, Wcpl, 2048, 1024);
    colprep<<<2048, 256, 0, s2>>>(b_pmu, b_pstd, Wcph, Wcpl, 2048, bcp, ccp);
    cudaEventRecord(evP2, s2);

    // ---- s0: prior chain ----
    cudaStreamWaitEvent(0, evWi, 0);
    gemm_mma<<<gN6, 128, SMEMB, 0>>>(h1h, h1l, Wih, Wil, bi, nullptr,
        giF, nullptr, nullptr, 2048, 6144, 0);
    cudaStreamWaitEvent(0, evGh, 0);
    cudaStreamWaitEvent(0, evXq, 0);
    gru_gate_k<<<(B_ * D_) / 512, 256, 0, 0>>>(giF, ghF, prev_h, out + 3 * S_, dth, dtl, Xqh, Xql);
    cudaEventRecord(evGru, 0);

    // ---- s1: prior tail ----
    cudaStreamWaitEvent(s1, evGru, 0);
    cudaStreamWaitEvent(s1, evP2, 0);
    gemm_mma<<<gN2, 128, SMEMB, s1>>>(dth, dtl, Wp2h, Wp2l, b_p2, nullptr,
        nullptr, h2h, h2l, 2048, 2048, 1);
    gemm_mma<<<gN2, 128, SMEMB, s1>>>(h2h, h2l, Wcph, Wcpl, bcp, ccp,
        out, nullptr, nullptr, 2048, OUTW, 2);
    sample_k<<<(B_ * S_) / 512, 256, 0, s1>>>(out, 0, S_, 2 * S_, eps_prior);
    cudaEventRecord(evPrior, s1);

    // ---- s0: posterior chain ----
    cudaStreamWaitEvent(0, evC, 0);
    gemm_mma<<<gN2, 128, SMEMB, 0>>>(Xqh, Xql, Wq1h, Wq1l, b_q1, nullptr,
        nullptr, h1h, h1l, 4096, 2048, 1);
    gemm_mma<<<gN6, 128, SMEMB, 0>>>(h1h, h1l, Wih, Wil, bi, nullptr,
        giF, nullptr, nullptr, 2048, 6144, 0);
    gru_gate_k<<<(B_ * D_) / 512, 256, 0, 0>>>(giF, ghF, prev_h, nullptr, dqh, dql, nullptr, nullptr);
    gemm_mma<<<gN2, 128, SMEMB, 0>>>(dqh, dql, Wq2h, Wq2l, b_q2, nullptr,
        nullptr, h2qh, h2ql, 2048, 2048, 1);
    gemm_mma<<<gN2, 128, SMEMB, 0>>>(h2qh, h2ql, Wcqh, Wcql, bcq, ccq,
        out + 5 * S_, nullptr, nullptr, 2048, OUTW, 2);
    sample_k<<<(B_ * S_) / 512, 256, 0, 0>>>(out, 5 * S_, 6 * S_, 7 * S_, eps_post);

    cudaStreamWaitEvent(0, evPrior, 0);

    (void)in_sizes; (void)n_in; (void)out_size;
}